// round 13
// baseline (speedup 1.0000x reference)
#include <cuda_runtime.h>
#include <cuda_bf16.h>
#include <math.h>
#include <stdint.h>

#define H       1024
#define DIN     2048
#define KEY_DIM 1024
#define DICT_LEN 16384
#define A2C_H   512
#define N_ACT   1024
#define BB      256
#define FIVE_H  (5*H)
#define KTOT    3072
#define EPSN    1e-8f

// ---- output layout (float32, tuple order flattened) ----
#define OFF_A    0
#define OFF_PROB 256
#define OFF_V    512
#define OFF_ENT  768
#define OFF_H    1024
#define OFF_C    (OFF_H + BB*H)
#define OFF_BEST (OFF_C + BB*H)
#define OFF_NK   (OFF_BEST + 256)
#define OFF_NV   (OFF_NK + DICT_LEN*KEY_DIM)

// ---- scratch (static device globals; no allocation allowed) ----
__device__ float g_preact[BB*FIVE_H];
__device__ float g_qinv[BB];
__device__ __nv_bfloat16 g_qhi[BB*KEY_DIM];
__device__ __nv_bfloat16 g_qlo[BB*KEY_DIM];
__device__ __nv_bfloat16 g_ahi[BB*KTOT];
__device__ __nv_bfloat16 g_alo[BB*KTOT];
__device__ __nv_bfloat16 g_wthi[(size_t)FIVE_H*KTOT];
__device__ __nv_bfloat16 g_wtlo[(size_t)FIVE_H*KTOT];
__device__ unsigned long long g_ppack[128 * BB];  // [chunk][query]
__device__ float g_ha[BB*A2C_H];
__device__ float g_logits[BB*N_ACT];

__device__ __forceinline__ float sigmoidf_(float x) { return 1.0f / (1.0f + expf(-x)); }

__device__ __forceinline__ unsigned float_flip(float f) {
    unsigned u = __float_as_uint(f);
    return (u & 0x80000000u) ? ~u : (u | 0x80000000u);
}

__device__ __forceinline__ unsigned long long pack_vi(float v, int row) {
    return ((unsigned long long)float_flip(v) << 32) |
           (unsigned)(0x7FFFFFFFu - (unsigned)row);
}

// HMMA m16n8k16 bf16, fp32 accum
__device__ __forceinline__ void mma_bf16(float* c, const uint32_t* a,
                                         uint32_t b0, uint32_t b1) {
    asm volatile(
        "mma.sync.aligned.m16n8k16.row.col.f32.bf16.bf16.f32 "
        "{%0,%1,%2,%3}, {%4,%5,%6,%7}, {%8,%9}, {%0,%1,%2,%3};\n"
        : "+f"(c[0]), "+f"(c[1]), "+f"(c[2]), "+f"(c[3])
        : "r"(a[0]), "r"(a[1]), "r"(a[2]), "r"(a[3]), "r"(b0), "r"(b1));
}

// ldmatrix x4 (b16 8x8 tiles)
__device__ __forceinline__ void ldsm_x4(uint32_t& r0, uint32_t& r1,
                                        uint32_t& r2, uint32_t& r3, uint32_t a) {
    asm volatile("ldmatrix.sync.aligned.m8n8.x4.shared.b16 {%0,%1,%2,%3}, [%4];"
        : "=r"(r0), "=r"(r1), "=r"(r2), "=r"(r3) : "r"(a));
}

__device__ __forceinline__ void split_bf16(float v, __nv_bfloat16& hi, __nv_bfloat16& lo) {
    hi = __float2bfloat16(v);
    lo = __float2bfloat16(v - __bfloat162float(hi));
}

__device__ __forceinline__ uint32_t smem_u32(const void* p) {
    uint32_t a;
    asm("{ .reg .u64 t; cvta.to.shared.u64 t, %1; cvt.u32.u64 %0, t; }"
        : "=r"(a) : "l"(p));
    return a;
}

__device__ __forceinline__ void cp16(uint32_t s, const void* g) {
    asm volatile("cp.async.cg.shared.global [%0], [%1], 16;" :: "r"(s), "l"(g));
}
#define CP_COMMIT() asm volatile("cp.async.commit_group;" ::: "memory")
#define CP_WAIT0()  asm volatile("cp.async.wait_group 0;" ::: "memory")

// ---- Threefry-2x32-20 with key (0,1)  (jax.random.key(1)) ----
__device__ __forceinline__ void threefry01(unsigned x0, unsigned x1,
                                           unsigned &o0, unsigned &o1) {
    const unsigned ks0 = 0u, ks1 = 1u, ks2 = 0u ^ 1u ^ 0x1BD11BDAu;
    x0 += ks0; x1 += ks1;
#define ROTL(v,r) (((v) << (r)) | ((v) >> (32 - (r))))
#define RND(r) { x0 += x1; x1 = ROTL(x1, r); x1 ^= x0; }
    RND(13) RND(15) RND(26) RND(6)
    x0 += ks1; x1 += ks2 + 1u;
    RND(17) RND(29) RND(16) RND(24)
    x0 += ks2; x1 += ks0 + 2u;
    RND(13) RND(15) RND(26) RND(6)
    x0 += ks0; x1 += ks1 + 3u;
    RND(17) RND(29) RND(16) RND(24)
    x0 += ks1; x1 += ks2 + 4u;
    RND(13) RND(15) RND(26) RND(6)
    x0 += ks2; x1 += ks0 + 5u;
#undef RND
#undef ROTL
    o0 = x0; o1 = x1;
}

// partitionable threefry: counter (0, j), lanes XOR'd
__device__ __forceinline__ float gumbel_at(int j) {
    unsigned o0, o1;
    threefry01(0u, (unsigned)j, o0, o1);
    unsigned bits = o0 ^ o1;
    float f = __uint_as_float((bits >> 9) | 0x3f800000u) - 1.0f;
    const float TINY = 1.1754943508222875e-38f;
    float u = fmaxf(TINY, f * (1.0f - TINY) + TINY);
    return -logf(-logf(u));
}

// ================= kernels =================

// q row inv-norms + bf16 hi/lo split (merged)
__global__ __launch_bounds__(128) void k_qprep(const float* __restrict__ q) {
    int row = blockIdx.x;
    int t = threadIdx.x;
    const float4* sq = (const float4*)(q + (size_t)row * KEY_DIM);
    float ss = 0.f;
    #pragma unroll
    for (int i = t; i < KEY_DIM/4; i += 128) {
        float4 v = sq[i];
        ss += v.x*v.x + v.y*v.y + v.z*v.z + v.w*v.w;
        __nv_bfloat16 h0,h1,h2,h3,l0,l1,l2,l3;
        split_bf16(v.x,h0,l0); split_bf16(v.y,h1,l1);
        split_bf16(v.z,h2,l2); split_bf16(v.w,h3,l3);
        __nv_bfloat162 ph0(h0,h1), ph1(h2,h3), pl0(l0,l1), pl1(l2,l3);
        size_t o = (size_t)row*KEY_DIM + i*4;
        *(__nv_bfloat162*)(g_qhi + o) = ph0;
        *(__nv_bfloat162*)(g_qhi + o + 2) = ph1;
        *(__nv_bfloat162*)(g_qlo + o) = pl0;
        *(__nv_bfloat162*)(g_qlo + o + 2) = pl1;
    }
    #pragma unroll
    for (int o = 16; o > 0; o >>= 1) ss += __shfl_down_sync(0xffffffffu, ss, o);
    __shared__ float w[4];
    if ((t & 31) == 0) w[t >> 5] = ss;
    __syncthreads();
    if (t == 0) {
        float s = w[0] + w[1] + w[2] + w[3];
        g_qinv[row] = 1.0f / fmaxf(sqrtf(s), EPSN);
    }
}

// split concat(obs, h) into bf16 hi/lo [256][3072]
__global__ __launch_bounds__(256) void k_asplit(
    const float* __restrict__ obs, const float* __restrict__ hin) {
    int idx = blockIdx.x * 256 + threadIdx.x;  // 256*3072
    int m = idx / KTOT;
    int k = idx - m * KTOT;
    float v = (k < DIN) ? obs[(size_t)m*DIN + k] : hin[(size_t)m*H + (k - DIN)];
    __nv_bfloat16 hi, lo;
    split_bf16(v, hi, lo);
    g_ahi[idx] = hi;
    g_alo[idx] = lo;
}

// transpose + split W = concat_k(Wi, Wh) [3072][5120] -> Wt [5120][3072] bf16 hi/lo
__global__ void k_wtrans(const float* __restrict__ Wi, const float* __restrict__ Wh) {
    __shared__ float tile[32][33];
    int k0 = blockIdx.x * 32, n0 = blockIdx.y * 32;
    int tx = threadIdx.x, ty = threadIdx.y;  // (32, 8)
    #pragma unroll
    for (int i = 0; i < 4; i++) {
        int k = k0 + ty + i*8;
        float v = (k < DIN) ? Wi[(size_t)k*FIVE_H + n0 + tx]
                            : Wh[(size_t)(k - DIN)*FIVE_H + n0 + tx];
        tile[ty + i*8][tx] = v;
    }
    __syncthreads();
    #pragma unroll
    for (int i = 0; i < 4; i++) {
        int n = n0 + ty + i*8;
        int k = k0 + tx;
        __nv_bfloat16 hi, lo;
        split_bf16(tile[tx][ty + i*8], hi, lo);
        g_wthi[(size_t)n*KTOT + k] = hi;
        g_wtlo[(size_t)n*KTOT + k] = lo;
    }
}

// K-chunk = 64; pitch 144B rows (conflict-free ldmatrix)
#define SPITCH 144
#define S_AL 18432      // sims: A lo   (A hi at 0; 128 rows * 144B)
#define S_B  36864      // sims: B hi   (256 rows * 144B)
#define S_BL 73728      // sims: B lo
#define SIMS_SBUF 110592
#define SIMS_SMEM (3584 + 2*SIMS_SBUF)   // 224768
#define P_AL 9216       // preact: A lo (A hi at 0; 64 rows * 144B)
#define P_B  18432      // preact: B hi (128 rows * 144B)
#define P_BL 36864      // preact: B lo

// ---- sims role: CTA 128 keys x 256 queries, 512 thr; fused dict copies ----
__device__ __forceinline__ void sims_body(char* dsm, const float* __restrict__ mk,
                                          const float* __restrict__ mv,
                                          float* __restrict__ nk,
                                          float* __restrict__ nv, int bid) {
    float* sq = (float*)dsm;
    unsigned long long* sbest = (unsigned long long*)(dsm + 1024);
    float* skin = (float*)(dsm + 3072);
    uint32_t sb32 = smem_u32(dsm);
    int tid = threadIdx.x;
    int lane = tid & 31, wid = tid >> 5;
    int g = lane >> 2, t2 = (lane & 3) * 2;
    int wm = wid >> 2, wn = wid & 3;          // 4 x 4 warps, tile 32x64
    int r0 = bid * 128;
    int lrow16 = lane & 15, lk8 = (lane >> 4) * 8;            // A tiles
    int brow8 = lane & 7, bk8 = ((lane >> 3) & 1) * 8, bn8 = (lane >> 4) * 8; // B tiles

    if (tid < 256) { sq[tid] = g_qinv[tid]; sbest[tid] = 0ull; }

    // per-thread A addressing: u = tid + i*512 (i<4), row = u>>4, kq = u&15
    int arow[4], akq[4];
    #pragma unroll
    for (int i = 0; i < 4; i++) { int u = tid + i*512; arow[i] = u >> 4; akq[i] = u & 15; }

    float acc[2][8][4];
    #pragma unroll
    for (int a = 0; a < 2; a++)
        #pragma unroll
        for (int b = 0; b < 8; b++)
            #pragma unroll
            for (int c = 0; c < 4; c++) acc[a][b][c] = 0.f;

    auto issueB = [&](int c, uint32_t bufo) {
        #pragma unroll
        for (int i = 0; i < 4; i++) {
            int u = tid + i*512;              // 0..2047
            int row = u >> 3, un = u & 7;     // 256 rows x 8 uint4
            uint32_t so = bufo + S_B + row*SPITCH + un*16;
            cp16(sb32 + so, g_qhi + (size_t)row*KEY_DIM + c*64 + un*8);
            cp16(sb32 + so + (S_BL - S_B), g_qlo + (size_t)row*KEY_DIM + c*64 + un*8);
        }
    };

    float4 ra[4];
    float ss[4] = {0.f, 0.f, 0.f, 0.f};
    #pragma unroll
    for (int i = 0; i < 4; i++)
        ra[i] = *(const float4*)(mk + (size_t)(r0+arow[i])*KEY_DIM + akq[i]*4);
    issueB(0, 3584);
    CP_COMMIT();

    for (int c = 0; c < 16; c++) {
        int b = c & 1;
        uint32_t bufo = 3584 + b*SIMS_SBUF;
        char* smA = dsm + bufo;
        float4 rn[4];
        if (c + 1 < 16) {
            #pragma unroll
            for (int i = 0; i < 4; i++)
                rn[i] = *(const float4*)(mk + (size_t)(r0+arow[i])*KEY_DIM
                                         + (c+1)*64 + akq[i]*4);
        }
        #pragma unroll
        for (int i = 0; i < 4; i++) {
            float4 v = ra[i];
            // fused dict-key copy
            *(float4*)(nk + (size_t)(r0+arow[i])*KEY_DIM + c*64 + akq[i]*4) = v;
            ss[i] += v.x*v.x + v.y*v.y + v.z*v.z + v.w*v.w;
            __nv_bfloat16 h0,h1,h2,h3,l0,l1,l2,l3;
            split_bf16(v.x,h0,l0); split_bf16(v.y,h1,l1);
            split_bf16(v.z,h2,l2); split_bf16(v.w,h3,l3);
            __nv_bfloat162 ph0(h0,h1), ph1(h2,h3), pl0(l0,l1), pl1(l2,l3);
            uint2 ph = make_uint2(*(unsigned*)&ph0, *(unsigned*)&ph1);
            uint2 pl = make_uint2(*(unsigned*)&pl0, *(unsigned*)&pl1);
            *(uint2*)(smA + arow[i]*SPITCH + akq[i]*8) = ph;
            *(uint2*)(smA + S_AL + arow[i]*SPITCH + akq[i]*8) = pl;
        }
        CP_WAIT0();
        __syncthreads();
        if (c + 1 < 16) {
            issueB(c+1, 3584 + (1-b)*SIMS_SBUF);
            CP_COMMIT();
        }
        #pragma unroll
        for (int ks = 0; ks < 4; ks++) {
            uint32_t ah[2][4], al[2][4];
            #pragma unroll
            for (int mt = 0; mt < 2; mt++) {
                uint32_t addr = sb32 + bufo +
                    (uint32_t)((wm*32 + mt*16 + lrow16)*SPITCH + (ks*16 + lk8)*2);
                ldsm_x4(ah[mt][0], ah[mt][1], ah[mt][2], ah[mt][3], addr);
                ldsm_x4(al[mt][0], al[mt][1], al[mt][2], al[mt][3], addr + S_AL);
            }
            #pragma unroll
            for (int p = 0; p < 4; p++) {
                uint32_t baddr = sb32 + bufo + S_B +
                    (uint32_t)((wn*64 + p*16 + bn8 + brow8)*SPITCH + (ks*16 + bk8)*2);
                uint32_t bh[4], bl[4];
                ldsm_x4(bh[0], bh[1], bh[2], bh[3], baddr);
                ldsm_x4(bl[0], bl[1], bl[2], bl[3], baddr + (S_BL - S_B));
                #pragma unroll
                for (int mt = 0; mt < 2; mt++) {
                    mma_bf16(acc[mt][2*p],   ah[mt], bh[0], bh[1]);
                    mma_bf16(acc[mt][2*p],   ah[mt], bl[0], bl[1]);
                    mma_bf16(acc[mt][2*p],   al[mt], bh[0], bh[1]);
                    mma_bf16(acc[mt][2*p+1], ah[mt], bh[2], bh[3]);
                    mma_bf16(acc[mt][2*p+1], ah[mt], bl[2], bl[3]);
                    mma_bf16(acc[mt][2*p+1], al[mt], bh[2], bh[3]);
                }
            }
        }
        if (c + 1 < 16) {
            #pragma unroll
            for (int i = 0; i < 4; i++) ra[i] = rn[i];
        }
    }

    // kinv: 16 threads share a row
    #pragma unroll
    for (int i = 0; i < 4; i++) {
        float s = ss[i];
        #pragma unroll
        for (int o = 8; o > 0; o >>= 1) s += __shfl_down_sync(0xffffffffu, s, o, 16);
        if ((tid & 15) == 0) skin[arow[i]] = 1.0f / fmaxf(sqrtf(s), EPSN);
    }
    __syncthreads();

    float kin[2][2];
    #pragma unroll
    for (int mt = 0; mt < 2; mt++) {
        int r_ = wm*32 + mt*16 + g;
        kin[mt][0] = skin[r_];
        kin[mt][1] = skin[r_ + 8];
    }
    #pragma unroll
    for (int j = 0; j < 8; j++) {
        int c_ = wn*64 + j*8 + t2;
        float q0 = sq[c_], q1 = sq[c_ + 1];
        unsigned long long m0p = 0ull, m1p = 0ull;
        #pragma unroll
        for (int mt = 0; mt < 2; mt++) {
            int r_ = r0 + wm*32 + mt*16 + g;
            unsigned long long p;
            p = pack_vi(acc[mt][j][0] * kin[mt][0] * q0, r_);     if (p > m0p) m0p = p;
            p = pack_vi(acc[mt][j][2] * kin[mt][1] * q0, r_ + 8); if (p > m0p) m0p = p;
            p = pack_vi(acc[mt][j][1] * kin[mt][0] * q1, r_);     if (p > m1p) m1p = p;
            p = pack_vi(acc[mt][j][3] * kin[mt][1] * q1, r_ + 8); if (p > m1p) m1p = p;
        }
        atomicMax(&sbest[c_], m0p);
        atomicMax(&sbest[c_ + 1], m1p);
    }
    __syncthreads();
    if (tid < 256)
        g_ppack[(size_t)bid * BB + tid] = sbest[tid];

    // fused dict-val copy: this CTA's 128 mem_vals rows -> new_vals (512 KB)
    {
        const float4* src = (const float4*)(mv + (size_t)r0 * H);
        float4* dst = (float4*)(nv + (size_t)r0 * H);
        #pragma unroll 4
        for (int i = tid; i < 128*H/4; i += 512) dst[i] = src[i];
    }
}

// ---- preact role: CTA 64x128 tile of [256 x 5120], 16 warps (2x8) ----
__device__ __forceinline__ void preact_body(char* dsm,
                                            const float* __restrict__ bi,
                                            const float* __restrict__ bh,
                                            int pb) {
    uint32_t sb32 = smem_u32(dsm);
    int tid = threadIdx.x;
    int lane = tid & 31, wid = tid >> 5;
    int g = lane >> 2, t2 = (lane & 3) * 2;
    int wm = wid >> 3, wn = wid & 7;          // 2 x 8 warps, warp tile 32x16
    int n0 = (pb % 40) * 128;
    int m0 = (pb / 40) * 64;
    int lrow16 = lane & 15, lk8 = (lane >> 4) * 8;
    int brow8 = lane & 7, bk8 = ((lane >> 3) & 1) * 8, bn8 = (lane >> 4) * 8;

    float acc[2][2][4];
    #pragma unroll
    for (int a = 0; a < 2; a++)
        #pragma unroll
        for (int b = 0; b < 2; b++)
            #pragma unroll
            for (int c = 0; c < 4; c++) acc[a][b][c] = 0.f;

    auto issueAB = [&](int kci, uint32_t bufo) {
        {   // A tile 64x64 bf16: 64 rows x 8 uint4, 512 threads = 1 each
            int row = tid >> 3, un = tid & 7;
            size_t src = (size_t)(m0 + row)*KTOT + kci*64 + un*8;
            uint32_t so = bufo + row*SPITCH + un*16;
            cp16(sb32 + so, g_ahi + src);
            cp16(sb32 + so + P_AL, g_alo + src);
        }
        #pragma unroll
        for (int i = 0; i < 2; i++) {  // B tile 128x64: 128 rows x 8 uint4
            int u = tid + i*512;
            int row = u >> 3, un = u & 7;
            size_t src = (size_t)(n0 + row)*KTOT + kci*64 + un*8;
            uint32_t so = bufo + P_B + row*SPITCH + un*16;
            cp16(sb32 + so, g_wthi + src);
            cp16(sb32 + so + (P_BL - P_B), g_wtlo + src);
        }
    };

    issueAB(0, 3584);
    CP_COMMIT();

    for (int kci = 0; kci < 48; kci++) {
        int b = kci & 1;
        uint32_t bufo = 3584 + b*SIMS_SBUF;
        CP_WAIT0();
        __syncthreads();
        if (kci + 1 < 48) {
            issueAB(kci + 1, (uint32_t)(3584 + (1-b)*SIMS_SBUF));
            CP_COMMIT();
        }
        #pragma unroll
        for (int ks = 0; ks < 4; ks++) {
            uint32_t ah[2][4], al[2][4];
            #pragma unroll
            for (int mt = 0; mt < 2; mt++) {
                uint32_t addr = sb32 + bufo +
                    (uint32_t)((wm*32 + mt*16 + lrow16)*SPITCH + (ks*16 + lk8)*2);
                ldsm_x4(ah[mt][0], ah[mt][1], ah[mt][2], ah[mt][3], addr);
                ldsm_x4(al[mt][0], al[mt][1], al[mt][2], al[mt][3], addr + P_AL);
            }
            {
                uint32_t baddr = sb32 + bufo + P_B +
                    (uint32_t)((wn*16 + bn8 + brow8)*SPITCH + (ks*16 + bk8)*2);
                uint32_t bhf[4], blf[4];
                ldsm_x4(bhf[0], bhf[1], bhf[2], bhf[3], baddr);
                ldsm_x4(blf[0], blf[1], blf[2], blf[3], baddr + (P_BL - P_B));
                #pragma unroll
                for (int mt = 0; mt < 2; mt++) {
                    mma_bf16(acc[mt][0], ah[mt], bhf[0], bhf[1]);
                    mma_bf16(acc[mt][0], ah[mt], blf[0], blf[1]);
                    mma_bf16(acc[mt][0], al[mt], bhf[0], bhf[1]);
                    mma_bf16(acc[mt][1], ah[mt], bhf[2], bhf[3]);
                    mma_bf16(acc[mt][1], ah[mt], blf[2], blf[3]);
                    mma_bf16(acc[mt][1], al[mt], bhf[2], bhf[3]);
                }
            }
        }
    }
    #pragma unroll
    for (int mt = 0; mt < 2; mt++) {
        int m = m0 + wm*32 + mt*16 + g;
        #pragma unroll
        for (int j = 0; j < 2; j++) {
            int n = n0 + wn*16 + j*8 + t2;
            float b0 = bi[n] + bh[n], b1 = bi[n+1] + bh[n+1];
            *(float2*)(g_preact + (size_t)m*FIVE_H + n) =
                make_float2(acc[mt][j][0] + b0, acc[mt][j][1] + b1);
            *(float2*)(g_preact + (size_t)(m+8)*FIVE_H + n) =
                make_float2(acc[mt][j][2] + b0, acc[mt][j][3] + b1);
        }
    }
}

// ---- mega: 128 sims CTAs (+dict copy) + 160 preact CTAs in one launch ----
__global__ __launch_bounds__(512, 1) void k_mega(
    const float* __restrict__ mk, const float* __restrict__ mv,
    float* __restrict__ nk, float* __restrict__ nv,
    const float* __restrict__ bi, const float* __restrict__ bh) {
    extern __shared__ __align__(16) char dsm[];
    if (blockIdx.x < 128) sims_body(dsm, mk, mv, nk, nv, blockIdx.x);
    else                  preact_body(dsm, bi, bh, blockIdx.x - 128);
}

// fused: per-b argmax over 128 chunk partials + gates + DND readout + h/c
__global__ __launch_bounds__(256) void k_lstm(
    const float* __restrict__ c_in, const float* __restrict__ mv,
    float* __restrict__ out) {
    int b_ = blockIdx.x;          // 256 blocks, one per batch row
    int t = threadIdx.x;
    __shared__ unsigned long long s[128];
    __shared__ int sbesti;
    if (t < 128) s[t] = g_ppack[(size_t)t * BB + b_];
    __syncthreads();
    for (int st = 64; st > 0; st >>= 1) {
        if (t < st) {
            unsigned long long v = s[t + st];
            if (v > s[t]) s[t] = v;
        }
        __syncthreads();
    }
    if (t == 0) {
        int best = (int)(0x7FFFFFFFu - (unsigned)(s[0] & 0xFFFFFFFFull));
        sbesti = best;
        out[OFF_BEST + b_] = (float)best;
    }
    __syncthreads();
    int best = sbesti;
    const float* p = g_preact + (size_t)b_ * FIVE_H;
    const float* mrow = mv + (size_t)best * H;
    #pragma unroll
    for (int r = 0; r < 4; r++) {
        int j = t + r*256;
        int idx = b_ * H + j;
        float f  = sigmoidf_(p[j]);
        float it = sigmoidf_(p[H + j]);
        float o  = sigmoidf_(p[2*H + j]);
        float rr = sigmoidf_(p[3*H + j]);
        float cn = tanhf(p[4*H + j]);
        float m  = tanhf(mrow[j]);
        float ct = f * c_in[idx] + it * cn + rr * m;
        float ht = o * tanhf(ct);
        out[OFF_H + idx] = ht;
        out[OFF_C + idx] = ct;
    }
}

// 32x64-tile fp32 GEMM: C = act(A[MxK] @ B[KxN] + bias)
template<int RELU>
__global__ __launch_bounds__(256) void k_gemm32(
    const float* __restrict__ A, const float* __restrict__ Bm,
    const float* __restrict__ bias, float* __restrict__ C,
    int M, int N, int K) {
    __shared__ float As[16][32];
    __shared__ float Bs[16][64];
    int n0 = blockIdx.x * 64;
    int m0 = blockIdx.y * 32;
    int t = threadIdx.x;
    int tx = t & 15, ty = t >> 4;     // 16 x 16
    float acc[2][4];
    #pragma unroll
    for (int i = 0; i < 2; i++)
        #pragma unroll
        for (int j = 0; j < 4; j++) acc[i][j] = 0.f;
    for (int k0 = 0; k0 < K; k0 += 16) {
        if (t < 128) {
            int row = t >> 2, kq = t & 3;
            float4 v = *(const float4*)(A + (size_t)(m0+row)*K + k0 + kq*4);
            As[kq*4+0][row] = v.x; As[kq*4+1][row] = v.y;
            As[kq*4+2][row] = v.z; As[kq*4+3][row] = v.w;
        }
        {
            int kk = t >> 4, nq = t & 15;
            *(float4*)&Bs[kk][nq*4] =
                *(const float4*)(Bm + (size_t)(k0+kk)*N + n0 + nq*4);
        }
        __syncthreads();
        #pragma unroll
        for (int kk = 0; kk < 16; kk++) {
            float a0 = As[kk][ty], a1 = As[kk][ty + 16];
            float b[4];
            #pragma unroll
            for (int j = 0; j < 4; j++) b[j] = Bs[kk][tx + j*16];
            #pragma unroll
            for (int j = 0; j < 4; j++) {
                acc[0][j] += a0 * b[j];
                acc[1][j] += a1 * b[j];
            }
        }
        __syncthreads();
    }
    #pragma unroll
    for (int i = 0; i < 2; i++) {
        int m = m0 + ty + i*16;
        #pragma unroll
        for (int j = 0; j < 4; j++) {
            int n = n0 + tx + j*16;
            float v = acc[i][j] + bias[n];
            if (RELU) v = fmaxf(v, 0.f);
            C[(size_t)m*N + n] = v;
        }
    }
}

// per-row: log_softmax stats, entropy, critic value, gumbel-argmax sample
__global__ __launch_bounds__(256) void k_final(
    const float* __restrict__ Wc, const float* __restrict__ bc,
    float* __restrict__ out) {
    int b_ = blockIdx.x;
    int t = threadIdx.x;
    __shared__ float sred[256];
    __shared__ float sgv[256];
    __shared__ int   sgi[256];
    const float* lrow = g_logits + (size_t)b_ * N_ACT;
    float l[4];
    #pragma unroll
    for (int k = 0; k < 4; k++) l[k] = lrow[t + k*256];

    float mx = fmaxf(fmaxf(l[0], l[1]), fmaxf(l[2], l[3]));
    sred[t] = mx; __syncthreads();
    for (int s = 128; s > 0; s >>= 1) {
        if (t < s) sred[t] = fmaxf(sred[t], sred[t+s]);
        __syncthreads();
    }
    mx = sred[0]; __syncthreads();

    float se = 0.f;
    #pragma unroll
    for (int k = 0; k < 4; k++) se += expf(l[k] - mx);
    sred[t] = se; __syncthreads();
    for (int s = 128; s > 0; s >>= 1) {
        if (t < s) sred[t] += sred[t+s];
        __syncthreads();
    }
    float lse = mx + logf(sred[0]); __syncthreads();

    float ent = 0.f;
    #pragma unroll
    for (int k = 0; k < 4; k++) {
        float lp = l[k] - lse;
        ent += expf(lp) * lp;
    }
    sred[t] = ent; __syncthreads();
    for (int s = 128; s > 0; s >>= 1) {
        if (t < s) sred[t] += sred[t+s];
        __syncthreads();
    }
    float entropy = -sred[0]; __syncthreads();

    const float* ha = g_ha + (size_t)b_ * A2C_H;
    float v = ha[t] * Wc[t] + ha[t + 256] * Wc[t + 256];
    sred[t] = v; __syncthreads();
    for (int s = 128; s > 0; s >>= 1) {
        if (t < s) sred[t] += sred[t+s];
        __syncthreads();
    }
    float vt = sred[0] + bc[0];

    float bv = -3.0e38f; int bn = 0;
    #pragma unroll
    for (int k = 0; k < 4; k++) {
        int n = t + k*256;
        float g = gumbel_at(b_ * N_ACT + n);
        float cand = (l[k] - lse) + g;
        if (cand > bv) { bv = cand; bn = n; }
    }
    sgv[t] = bv; sgi[t] = bn; __syncthreads();
    for (int s = 128; s > 0; s >>= 1) {
        if (t < s) {
            if (sgv[t+s] > sgv[t] || (sgv[t+s] == sgv[t] && sgi[t+s] < sgi[t])) {
                sgv[t] = sgv[t+s]; sgi[t] = sgi[t+s];
            }
        }
        __syncthreads();
    }
    if (t == 0) {
        int nbest = sgi[0];
        out[OFF_A + b_] = (float)nbest;
        out[OFF_PROB + b_] = lrow[nbest] - lse;
        out[OFF_V + b_] = vt;
        out[OFF_ENT + b_] = entropy;
    }
}

// last-write-wins scatter of q_t / c_t into the dict copies
__global__ __launch_bounds__(256) void k_scatter(
    const int* __restrict__ widx, const float* __restrict__ q,
    float* __restrict__ out) {
    int b_ = blockIdx.x;
    __shared__ int target;
    if (threadIdx.x == 0) {
        int idx = widx[b_];
        int last = 1;
        for (int b2 = b_ + 1; b2 < BB; b2++)
            if (widx[b2] == idx) { last = 0; break; }
        target = last ? idx : -1;
    }
    __syncthreads();
    int idx = target;
    if (idx < 0) return;
    int t = threadIdx.x;
    const float4* qs = (const float4*)(q + (size_t)b_ * KEY_DIM);
    const float4* cs = (const float4*)(out + OFF_C + (size_t)b_ * H);
    float4* kd = (float4*)(out + OFF_NK + (size_t)idx * KEY_DIM);
    float4* vd = (float4*)(out + OFF_NV + (size_t)idx * H);
    kd[t] = qs[t];
    vd[t] = cs[t];
}

extern "C" void kernel_launch(void* const* d_in, const int* in_sizes, int n_in,
                              void* d_out, int out_size) {
    const float* obs     = (const float*)d_in[0];
    const float* barcode = (const float*)d_in[1];
    const float* h_in    = (const float*)d_in[2];
    const float* c_in    = (const float*)d_in[3];
    const int*   widx    = (const int*)  d_in[4];
    const float* Wi      = (const float*)d_in[5];
    const float* bi      = (const float*)d_in[6];
    const float* Wh      = (const float*)d_in[7];
    const float* bh      = (const float*)d_in[8];
    const float* mk      = (const float*)d_in[9];
    const float* mv      = (const float*)d_in[10];
    const float* Wa      = (const float*)d_in[11];
    const float* ba      = (const float*)d_in[12];
    const float* Wact    = (const float*)d_in[13];
    const float* bact    = (const float*)d_in[14];
    const float* Wc      = (const float*)d_in[15];
    const float* bc      = (const float*)d_in[16];
    float* out = (float*)d_out;

    float* g_ha_ptr; cudaGetSymbolAddress((void**)&g_ha_ptr, g_ha);
    float* g_logits_ptr; cudaGetSymbolAddress((void**)&g_logits_ptr, g_logits);

    static int initd = 0;
    if (!initd) {
        cudaFuncSetAttribute(k_mega, cudaFuncAttributeMaxDynamicSharedMemorySize,
                             SIMS_SMEM);
        initd = 1;
    }

    // single stream — mega owns the whole chip anyway (full RF/SM)
    k_qprep<<<BB, 128>>>(barcode);                                        // #1
    k_asplit<<<BB*KTOT/256, 256>>>(obs, h_in);                            // #2
    k_wtrans<<<dim3(KTOT/32, FIVE_H/32), dim3(32, 8)>>>(Wi, Wh);          // #3
    k_mega<<<288, 512, SIMS_SMEM>>>(mk, mv, out + OFF_NK, out + OFF_NV,
                                    bi, bh);                              // #4 (profiled)
    k_lstm<<<BB, 256>>>(c_in, mv, out);                                   // #5
    k_scatter<<<BB, 256>>>(widx, barcode, out);                           // #6
    // ha = relu(c_t @ Wa + ba)
    k_gemm32<1><<<dim3(A2C_H/64, BB/32), 256>>>(out + OFF_C, Wa, ba, g_ha_ptr,
                                                BB, A2C_H, H);            // #7
    // logits = ha @ W_actor + b_actor
    k_gemm32<0><<<dim3(N_ACT/64, BB/32), 256>>>(g_ha_ptr, Wact, bact, g_logits_ptr,
                                                BB, N_ACT, A2C_H);        // #8
    k_final<<<BB, 256>>>(Wc, bc, out);                                    // #9
}

// round 14
// speedup vs baseline: 1.1270x; 1.1270x over previous
#include <cuda_runtime.h>
#include <cuda_bf16.h>
#include <math.h>
#include <stdint.h>

#define H       1024
#define DIN     2048
#define KEY_DIM 1024
#define DICT_LEN 16384
#define A2C_H   512
#define N_ACT   1024
#define BB      256
#define FIVE_H  (5*H)
#define KTOT    3072
#define EPSN    1e-8f

// ---- output layout (float32, tuple order flattened) ----
#define OFF_A    0
#define OFF_PROB 256
#define OFF_V    512
#define OFF_ENT  768
#define OFF_H    1024
#define OFF_C    (OFF_H + BB*H)
#define OFF_BEST (OFF_C + BB*H)
#define OFF_NK   (OFF_BEST + 256)
#define OFF_NV   (OFF_NK + DICT_LEN*KEY_DIM)

// ---- scratch (static device globals; no allocation allowed) ----
__device__ float g_preact[BB*FIVE_H];
__device__ float g_qinv[BB];
__device__ __nv_bfloat16 g_qhi[BB*KEY_DIM];
__device__ __nv_bfloat16 g_qlo[BB*KEY_DIM];
__device__ __nv_bfloat16 g_ahi[BB*KTOT];
__device__ __nv_bfloat16 g_alo[BB*KTOT];
__device__ __nv_bfloat16 g_wthi[(size_t)FIVE_H*KTOT];
__device__ __nv_bfloat16 g_wtlo[(size_t)FIVE_H*KTOT];
__device__ unsigned long long g_ppack[128 * BB];  // [chunk][query]
__device__ float g_ha[BB*A2C_H];
__device__ float g_logits[BB*N_ACT];

__device__ __forceinline__ float sigmoidf_(float x) { return 1.0f / (1.0f + expf(-x)); }

__device__ __forceinline__ unsigned float_flip(float f) {
    unsigned u = __float_as_uint(f);
    return (u & 0x80000000u) ? ~u : (u | 0x80000000u);
}

__device__ __forceinline__ unsigned long long pack_vi(float v, int row) {
    return ((unsigned long long)float_flip(v) << 32) |
           (unsigned)(0x7FFFFFFFu - (unsigned)row);
}

// HMMA m16n8k16 bf16, fp32 accum
__device__ __forceinline__ void mma_bf16(float* c, const uint32_t* a,
                                         uint32_t b0, uint32_t b1) {
    asm volatile(
        "mma.sync.aligned.m16n8k16.row.col.f32.bf16.bf16.f32 "
        "{%0,%1,%2,%3}, {%4,%5,%6,%7}, {%8,%9}, {%0,%1,%2,%3};\n"
        : "+f"(c[0]), "+f"(c[1]), "+f"(c[2]), "+f"(c[3])
        : "r"(a[0]), "r"(a[1]), "r"(a[2]), "r"(a[3]), "r"(b0), "r"(b1));
}

// ldmatrix x4 (b16 8x8 tiles)
__device__ __forceinline__ void ldsm_x4(uint32_t& r0, uint32_t& r1,
                                        uint32_t& r2, uint32_t& r3, uint32_t a) {
    asm volatile("ldmatrix.sync.aligned.m8n8.x4.shared.b16 {%0,%1,%2,%3}, [%4];"
        : "=r"(r0), "=r"(r1), "=r"(r2), "=r"(r3) : "r"(a));
}

__device__ __forceinline__ void split_bf16(float v, __nv_bfloat16& hi, __nv_bfloat16& lo) {
    hi = __float2bfloat16(v);
    lo = __float2bfloat16(v - __bfloat162float(hi));
}

__device__ __forceinline__ unsigned pack_bf2(__nv_bfloat16 a, __nv_bfloat16 b) {
    __nv_bfloat162 t(a, b);
    return *reinterpret_cast<unsigned*>(&t);
}

__device__ __forceinline__ uint32_t smem_u32(const void* p) {
    uint32_t a;
    asm("{ .reg .u64 t; cvta.to.shared.u64 t, %1; cvt.u32.u64 %0, t; }"
        : "=r"(a) : "l"(p));
    return a;
}

__device__ __forceinline__ void cp16(uint32_t s, const void* g) {
    asm volatile("cp.async.cg.shared.global [%0], [%1], 16;" :: "r"(s), "l"(g));
}
#define CP_COMMIT() asm volatile("cp.async.commit_group;" ::: "memory")
#define CP_WAIT0()  asm volatile("cp.async.wait_group 0;" ::: "memory")

// ---- Threefry-2x32-20 with key (0,1)  (jax.random.key(1)) ----
__device__ __forceinline__ void threefry01(unsigned x0, unsigned x1,
                                           unsigned &o0, unsigned &o1) {
    const unsigned ks0 = 0u, ks1 = 1u, ks2 = 0u ^ 1u ^ 0x1BD11BDAu;
    x0 += ks0; x1 += ks1;
#define ROTL(v,r) (((v) << (r)) | ((v) >> (32 - (r))))
#define RND(r) { x0 += x1; x1 = ROTL(x1, r); x1 ^= x0; }
    RND(13) RND(15) RND(26) RND(6)
    x0 += ks1; x1 += ks2 + 1u;
    RND(17) RND(29) RND(16) RND(24)
    x0 += ks2; x1 += ks0 + 2u;
    RND(13) RND(15) RND(26) RND(6)
    x0 += ks0; x1 += ks1 + 3u;
    RND(17) RND(29) RND(16) RND(24)
    x0 += ks1; x1 += ks2 + 4u;
    RND(13) RND(15) RND(26) RND(6)
    x0 += ks2; x1 += ks0 + 5u;
#undef RND
#undef ROTL
    o0 = x0; o1 = x1;
}

// partitionable threefry: counter (0, j), lanes XOR'd
__device__ __forceinline__ float gumbel_at(int j) {
    unsigned o0, o1;
    threefry01(0u, (unsigned)j, o0, o1);
    unsigned bits = o0 ^ o1;
    float f = __uint_as_float((bits >> 9) | 0x3f800000u) - 1.0f;
    const float TINY = 1.1754943508222875e-38f;
    float u = fmaxf(TINY, f * (1.0f - TINY) + TINY);
    return -logf(-logf(u));
}

// ================= kernels =================

// q row inv-norms + bf16 hi/lo split (merged)
__global__ __launch_bounds__(128) void k_qprep(const float* __restrict__ q) {
    int row = blockIdx.x;
    int t = threadIdx.x;
    const float4* sq = (const float4*)(q + (size_t)row * KEY_DIM);
    float ss = 0.f;
    #pragma unroll
    for (int i = t; i < KEY_DIM/4; i += 128) {
        float4 v = sq[i];
        ss += v.x*v.x + v.y*v.y + v.z*v.z + v.w*v.w;
        __nv_bfloat16 h0,h1,h2,h3,l0,l1,l2,l3;
        split_bf16(v.x,h0,l0); split_bf16(v.y,h1,l1);
        split_bf16(v.z,h2,l2); split_bf16(v.w,h3,l3);
        __nv_bfloat162 ph0(h0,h1), ph1(h2,h3), pl0(l0,l1), pl1(l2,l3);
        size_t o = (size_t)row*KEY_DIM + i*4;
        *(__nv_bfloat162*)(g_qhi + o) = ph0;
        *(__nv_bfloat162*)(g_qhi + o + 2) = ph1;
        *(__nv_bfloat162*)(g_qlo + o) = pl0;
        *(__nv_bfloat162*)(g_qlo + o + 2) = pl1;
    }
    #pragma unroll
    for (int o = 16; o > 0; o >>= 1) ss += __shfl_down_sync(0xffffffffu, ss, o);
    __shared__ float w[4];
    if ((t & 31) == 0) w[t >> 5] = ss;
    __syncthreads();
    if (t == 0) {
        float s = w[0] + w[1] + w[2] + w[3];
        g_qinv[row] = 1.0f / fmaxf(sqrtf(s), EPSN);
    }
}

// split concat(obs, h) into bf16 hi/lo [256][3072]
__global__ __launch_bounds__(256) void k_asplit(
    const float* __restrict__ obs, const float* __restrict__ hin) {
    int idx = blockIdx.x * 256 + threadIdx.x;  // 256*3072
    int m = idx / KTOT;
    int k = idx - m * KTOT;
    float v = (k < DIN) ? obs[(size_t)m*DIN + k] : hin[(size_t)m*H + (k - DIN)];
    __nv_bfloat16 hi, lo;
    split_bf16(v, hi, lo);
    g_ahi[idx] = hi;
    g_alo[idx] = lo;
}

// transpose + split W -> Wt [5120][3072] bf16 hi/lo; 64x64 tiles, uint4 writes
__global__ __launch_bounds__(256) void k_wtrans(
    const float* __restrict__ Wi, const float* __restrict__ Wh) {
    __shared__ float tile[64][65];
    int k0 = blockIdx.x * 64, n0 = blockIdx.y * 64;
    int t = threadIdx.x;
    #pragma unroll
    for (int i = 0; i < 4; i++) {
        int u = t + i*256;           // 0..1023
        int row = u >> 4, c4 = u & 15;
        int k = k0 + row;
        const float* src = (k < DIN) ? (Wi + (size_t)k*FIVE_H + n0 + c4*4)
                                     : (Wh + (size_t)(k - DIN)*FIVE_H + n0 + c4*4);
        float4 v = *(const float4*)src;
        tile[row][c4*4+0] = v.x; tile[row][c4*4+1] = v.y;
        tile[row][c4*4+2] = v.z; tile[row][c4*4+3] = v.w;
    }
    __syncthreads();
    #pragma unroll
    for (int i = 0; i < 2; i++) {
        int u = t + i*256;           // 0..511
        int n = u >> 3, oct = u & 7;
        __nv_bfloat16 hv[8], lv[8];
        #pragma unroll
        for (int j = 0; j < 8; j++)
            split_bf16(tile[oct*8 + j][n], hv[j], lv[j]);
        uint4 ph, pl;
        ph.x = pack_bf2(hv[0], hv[1]); ph.y = pack_bf2(hv[2], hv[3]);
        ph.z = pack_bf2(hv[4], hv[5]); ph.w = pack_bf2(hv[6], hv[7]);
        pl.x = pack_bf2(lv[0], lv[1]); pl.y = pack_bf2(lv[2], lv[3]);
        pl.z = pack_bf2(lv[4], lv[5]); pl.w = pack_bf2(lv[6], lv[7]);
        *(uint4*)(g_wthi + (size_t)(n0+n)*KTOT + k0 + oct*8) = ph;
        *(uint4*)(g_wtlo + (size_t)(n0+n)*KTOT + k0 + oct*8) = pl;
    }
}

#define PPITCH 40   // bf16 elements per smem row (80 bytes)
#define SIMS_SBUF 61440
#define SIMS_SMEM (3584 + 2*SIMS_SBUF)

// ---- sims role: CTA 128 keys x 256 queries, 512 thr; fused dict copies ----
__device__ __forceinline__ void sims_body(char* dsm, const float* __restrict__ mk,
                                          const float* __restrict__ mv,
                                          float* __restrict__ nk,
                                          float* __restrict__ nv, int bid) {
    float* sq = (float*)dsm;
    unsigned long long* sbest = (unsigned long long*)(dsm + 1024);
    float* skin = (float*)(dsm + 3072);
    uint32_t sb32 = smem_u32(dsm);
    int tid = threadIdx.x;
    int lane = tid & 31, wid = tid >> 5;
    int g = lane >> 2, t2 = (lane & 3) * 2;
    int wm = wid >> 2, wn = wid & 3;          // 4 x 4 warps, tile 32x64
    int r0 = bid * 128;
    int lrow16 = lane & 15, lk8 = (lane >> 4) * 8;            // A tiles
    int brow8 = lane & 7, bk8 = ((lane >> 3) & 1) * 8, bn8 = (lane >> 4) * 8; // B tiles

    if (tid < 256) { sq[tid] = g_qinv[tid]; sbest[tid] = 0ull; }

    int arow[2], akq[2];
    #pragma unroll
    for (int i = 0; i < 2; i++) { int u = tid + i*512; arow[i] = u >> 3; akq[i] = u & 7; }

    float acc[2][8][4];
    #pragma unroll
    for (int a = 0; a < 2; a++)
        #pragma unroll
        for (int b = 0; b < 8; b++)
            #pragma unroll
            for (int c = 0; c < 4; c++) acc[a][b][c] = 0.f;

    auto issueB = [&](int c, uint32_t bufo) {
        #pragma unroll
        for (int i = 0; i < 2; i++) {
            int u = tid + i*512;
            int row = u >> 2, un = u & 3;
            uint32_t so = bufo + 20480 + row*80 + un*16;      // Bh
            cp16(sb32 + so, g_qhi + (size_t)row*KEY_DIM + c*32 + un*8);
            cp16(sb32 + so + 20480, g_qlo + (size_t)row*KEY_DIM + c*32 + un*8);
        }
    };

    float4 ra[2];
    float ss[2] = {0.f, 0.f};
    #pragma unroll
    for (int i = 0; i < 2; i++)
        ra[i] = *(const float4*)(mk + (size_t)(r0+arow[i])*KEY_DIM + akq[i]*4);
    issueB(0, 3584);
    CP_COMMIT();

    for (int c = 0; c < 32; c++) {
        int b = c & 1;
        uint32_t bufo = 3584 + b*SIMS_SBUF;
        char* smA = dsm + bufo;
        float4 rn[2];
        if (c + 1 < 32) {
            #pragma unroll
            for (int i = 0; i < 2; i++)
                rn[i] = *(const float4*)(mk + (size_t)(r0+arow[i])*KEY_DIM
                                         + (c+1)*32 + akq[i]*4);
        }
        #pragma unroll
        for (int i = 0; i < 2; i++) {
            float4 v = ra[i];
            // fused dict-key copy: same data, coalesced STG.128
            *(float4*)(nk + (size_t)(r0+arow[i])*KEY_DIM + c*32 + akq[i]*4) = v;
            ss[i] += v.x*v.x + v.y*v.y + v.z*v.z + v.w*v.w;
            __nv_bfloat16 h0,h1,h2,h3,l0,l1,l2,l3;
            split_bf16(v.x,h0,l0); split_bf16(v.y,h1,l1);
            split_bf16(v.z,h2,l2); split_bf16(v.w,h3,l3);
            uint2 ph = make_uint2(pack_bf2(h0,h1), pack_bf2(h2,h3));
            uint2 pl = make_uint2(pack_bf2(l0,l1), pack_bf2(l2,l3));
            *(uint2*)(smA + arow[i]*80 + akq[i]*8) = ph;
            *(uint2*)(smA + 10240 + arow[i]*80 + akq[i]*8) = pl;
        }
        CP_WAIT0();
        __syncthreads();
        if (c + 1 < 32) {
            issueB(c+1, 3584 + (1-b)*SIMS_SBUF);
            CP_COMMIT();
        }
        #pragma unroll
        for (int ks = 0; ks < 2; ks++) {
            uint32_t ah[2][4], al[2][4];
            #pragma unroll
            for (int mt = 0; mt < 2; mt++) {
                uint32_t addr = sb32 + bufo +
                    (uint32_t)(((wm*32 + mt*16 + lrow16)*PPITCH + ks*16 + lk8)*2);
                ldsm_x4(ah[mt][0], ah[mt][1], ah[mt][2], ah[mt][3], addr);
                ldsm_x4(al[mt][0], al[mt][1], al[mt][2], al[mt][3], addr + 10240);
            }
            #pragma unroll
            for (int p = 0; p < 4; p++) {
                uint32_t baddr = sb32 + bufo + 20480 +
                    (uint32_t)(((wn*64 + p*16 + bn8 + brow8)*PPITCH + ks*16 + bk8)*2);
                uint32_t bh[4], bl[4];
                ldsm_x4(bh[0], bh[1], bh[2], bh[3], baddr);
                ldsm_x4(bl[0], bl[1], bl[2], bl[3], baddr + 20480);
                #pragma unroll
                for (int mt = 0; mt < 2; mt++) {
                    mma_bf16(acc[mt][2*p],   ah[mt], bh[0], bh[1]);
                    mma_bf16(acc[mt][2*p],   ah[mt], bl[0], bl[1]);
                    mma_bf16(acc[mt][2*p],   al[mt], bh[0], bh[1]);
                    mma_bf16(acc[mt][2*p+1], ah[mt], bh[2], bh[3]);
                    mma_bf16(acc[mt][2*p+1], ah[mt], bl[2], bl[3]);
                    mma_bf16(acc[mt][2*p+1], al[mt], bh[2], bh[3]);
                }
            }
        }
        if (c + 1 < 32) { ra[0] = rn[0]; ra[1] = rn[1]; }
    }

    #pragma unroll
    for (int i = 0; i < 2; i++) {
        float s = ss[i];
        #pragma unroll
        for (int o = 4; o > 0; o >>= 1) s += __shfl_down_sync(0xffffffffu, s, o, 8);
        if ((tid & 7) == 0) skin[arow[i]] = 1.0f / fmaxf(sqrtf(s), EPSN);
    }
    __syncthreads();

    float kin[2][2];
    #pragma unroll
    for (int mt = 0; mt < 2; mt++) {
        int r_ = wm*32 + mt*16 + g;
        kin[mt][0] = skin[r_];
        kin[mt][1] = skin[r_ + 8];
    }
    #pragma unroll
    for (int j = 0; j < 8; j++) {
        int c_ = wn*64 + j*8 + t2;
        float q0 = sq[c_], q1 = sq[c_ + 1];
        unsigned long long m0p = 0ull, m1p = 0ull;
        #pragma unroll
        for (int mt = 0; mt < 2; mt++) {
            int r_ = r0 + wm*32 + mt*16 + g;
            unsigned long long p;
            p = pack_vi(acc[mt][j][0] * kin[mt][0] * q0, r_);     if (p > m0p) m0p = p;
            p = pack_vi(acc[mt][j][2] * kin[mt][1] * q0, r_ + 8); if (p > m0p) m0p = p;
            p = pack_vi(acc[mt][j][1] * kin[mt][0] * q1, r_);     if (p > m1p) m1p = p;
            p = pack_vi(acc[mt][j][3] * kin[mt][1] * q1, r_ + 8); if (p > m1p) m1p = p;
        }
        atomicMax(&sbest[c_], m0p);
        atomicMax(&sbest[c_ + 1], m1p);
    }
    __syncthreads();
    if (tid < 256)
        g_ppack[(size_t)bid * BB + tid] = sbest[tid];

    // fused dict-val copy: this CTA's 128 mem_vals rows -> new_vals (512 KB)
    {
        const float4* src = (const float4*)(mv + (size_t)r0 * H);
        float4* dst = (float4*)(nv + (size_t)r0 * H);
        #pragma unroll 4
        for (int i = tid; i < 128*H/4; i += 512) dst[i] = src[i];
    }
}

// ---- preact role: CTA 64x128 tile of [256 x 5120], 16 warps (2x8) ----
__device__ __forceinline__ void preact_body(char* dsm,
                                            const float* __restrict__ bi,
                                            const float* __restrict__ bh,
                                            int pb) {
    uint32_t sb32 = smem_u32(dsm);
    int tid = threadIdx.x;
    int lane = tid & 31, wid = tid >> 5;
    int g = lane >> 2, t2 = (lane & 3) * 2;
    int wm = wid >> 3, wn = wid & 7;          // 2 x 8 warps, warp tile 32x16
    int n0 = (pb % 40) * 128;
    int m0 = (pb / 40) * 64;
    int lrow16 = lane & 15, lk8 = (lane >> 4) * 8;
    int brow8 = lane & 7, bk8 = ((lane >> 3) & 1) * 8, bn8 = (lane >> 4) * 8;

    float acc[2][2][4];
    #pragma unroll
    for (int a = 0; a < 2; a++)
        #pragma unroll
        for (int b = 0; b < 2; b++)
            #pragma unroll
            for (int c = 0; c < 4; c++) acc[a][b][c] = 0.f;

    auto issueAB = [&](int kci, uint32_t bufo) {
        if (tid < 256) {   // A tile 64x32: 64 rows x 4 uint4
            int row = tid >> 2, un = tid & 3;
            size_t src = (size_t)(m0 + row)*KTOT + kci*32 + un*8;
            uint32_t so = bufo + row*80 + un*16;
            cp16(sb32 + so, g_ahi + src);
            cp16(sb32 + so + 5120, g_alo + src);
        }
        {   // B tile 128x32: 128 rows x 4 uint4, all 512 threads
            int row = tid >> 2, un = tid & 3;
            size_t src = (size_t)(n0 + row)*KTOT + kci*32 + un*8;
            uint32_t so = bufo + 10240 + row*80 + un*16;
            cp16(sb32 + so, g_wthi + src);
            cp16(sb32 + so + 10240, g_wtlo + src);
        }
    };

    issueAB(0, 3584);
    CP_COMMIT();

    for (int kci = 0; kci < 96; kci++) {
        int b = kci & 1;
        uint32_t bufo = 3584 + b*SIMS_SBUF;
        CP_WAIT0();
        __syncthreads();
        if (kci + 1 < 96) {
            issueAB(kci + 1, (uint32_t)(3584 + (1-b)*SIMS_SBUF));
            CP_COMMIT();
        }
        #pragma unroll
        for (int ks = 0; ks < 2; ks++) {
            uint32_t ah[2][4], al[2][4];
            #pragma unroll
            for (int mt = 0; mt < 2; mt++) {
                uint32_t addr = sb32 + bufo +
                    (uint32_t)(((wm*32 + mt*16 + lrow16)*PPITCH + ks*16 + lk8)*2);
                ldsm_x4(ah[mt][0], ah[mt][1], ah[mt][2], ah[mt][3], addr);
                ldsm_x4(al[mt][0], al[mt][1], al[mt][2], al[mt][3], addr + 5120);
            }
            {
                uint32_t baddr = sb32 + bufo + 10240 +
                    (uint32_t)(((wn*16 + bn8 + brow8)*PPITCH + ks*16 + bk8)*2);
                uint32_t bhf[4], blf[4];
                ldsm_x4(bhf[0], bhf[1], bhf[2], bhf[3], baddr);
                ldsm_x4(blf[0], blf[1], blf[2], blf[3], baddr + 10240);
                #pragma unroll
                for (int mt = 0; mt < 2; mt++) {
                    mma_bf16(acc[mt][0], ah[mt], bhf[0], bhf[1]);
                    mma_bf16(acc[mt][0], ah[mt], blf[0], blf[1]);
                    mma_bf16(acc[mt][0], al[mt], bhf[0], bhf[1]);
                    mma_bf16(acc[mt][1], ah[mt], bhf[2], bhf[3]);
                    mma_bf16(acc[mt][1], ah[mt], blf[2], blf[3]);
                    mma_bf16(acc[mt][1], al[mt], bhf[2], bhf[3]);
                }
            }
        }
    }
    #pragma unroll
    for (int mt = 0; mt < 2; mt++) {
        int m = m0 + wm*32 + mt*16 + g;
        #pragma unroll
        for (int j = 0; j < 2; j++) {
            int n = n0 + wn*16 + j*8 + t2;
            float b0 = bi[n] + bh[n], b1 = bi[n+1] + bh[n+1];
            *(float2*)(g_preact + (size_t)m*FIVE_H + n) =
                make_float2(acc[mt][j][0] + b0, acc[mt][j][1] + b1);
            *(float2*)(g_preact + (size_t)(m+8)*FIVE_H + n) =
                make_float2(acc[mt][j][2] + b0, acc[mt][j][3] + b1);
        }
    }
}

// ---- mega: 128 sims CTAs (+dict copy) + 160 preact CTAs in one launch ----
__global__ __launch_bounds__(512, 1) void k_mega(
    const float* __restrict__ mk, const float* __restrict__ mv,
    float* __restrict__ nk, float* __restrict__ nv,
    const float* __restrict__ bi, const float* __restrict__ bh) {
    extern __shared__ __align__(16) char dsm[];
    if (blockIdx.x < 128) sims_body(dsm, mk, mv, nk, nv, blockIdx.x);
    else                  preact_body(dsm, bi, bh, blockIdx.x - 128);
}

// fused: per-b argmax + gates + DND readout + h/c + last-write-wins scatter
__global__ __launch_bounds__(256) void k_lstm(
    const float* __restrict__ c_in, const float* __restrict__ mv,
    const int* __restrict__ widx, const float* __restrict__ q,
    float* __restrict__ out) {
    int b_ = blockIdx.x;          // 256 blocks, one per batch row
    int t = threadIdx.x;
    __shared__ unsigned long long s[128];
    __shared__ int sbesti;
    __shared__ int sflag;
    if (t < 128) s[t] = g_ppack[(size_t)t * BB + b_];
    if (t == 0) sflag = 1;
    __syncthreads();
    for (int st = 64; st > 0; st >>= 1) {
        if (t < st) {
            unsigned long long v = s[t + st];
            if (v > s[t]) s[t] = v;
        }
        __syncthreads();
    }
    if (t == 0) {
        int best = (int)(0x7FFFFFFFu - (unsigned)(s[0] & 0xFFFFFFFFull));
        sbesti = best;
        out[OFF_BEST + b_] = (float)best;
    }
    int myidx = widx[b_];
    if (t > b_ && widx[t] == myidx) sflag = 0;   // later duplicate exists
    __syncthreads();
    int best = sbesti;
    const float* p = g_preact + (size_t)b_ * FIVE_H;
    const float* mrow = mv + (size_t)best * H;
    float ct_r[4];
    #pragma unroll
    for (int r = 0; r < 4; r++) {
        int j = t + r*256;
        int idx = b_ * H + j;
        float f  = sigmoidf_(p[j]);
        float it = sigmoidf_(p[H + j]);
        float o  = sigmoidf_(p[2*H + j]);
        float rr = sigmoidf_(p[3*H + j]);
        float cn = tanhf(p[4*H + j]);
        float m  = tanhf(mrow[j]);
        float ct = f * c_in[idx] + it * cn + rr * m;
        float ht = o * tanhf(ct);
        ct_r[r] = ct;
        out[OFF_H + idx] = ht;
        out[OFF_C + idx] = ct;
    }
    // scatter: if this row is the last writer to myidx, write q and c_t
    if (sflag) {
        #pragma unroll
        for (int r = 0; r < 4; r++) {
            int j = t + r*256;
            out[OFF_NK + (size_t)myidx*KEY_DIM + j] = q[(size_t)b_*KEY_DIM + j];
            out[OFF_NV + (size_t)myidx*H + j] = ct_r[r];
        }
    }
}

// 32x64-tile fp32 GEMM: C = act(A[MxK] @ B[KxN] + bias)
template<int RELU>
__global__ __launch_bounds__(256) void k_gemm32(
    const float* __restrict__ A, const float* __restrict__ Bm,
    const float* __restrict__ bias, float* __restrict__ C,
    int M, int N, int K) {
    __shared__ float As[16][32];
    __shared__ float Bs[16][64];
    int n0 = blockIdx.x * 64;
    int m0 = blockIdx.y * 32;
    int t = threadIdx.x;
    int tx = t & 15, ty = t >> 4;     // 16 x 16
    float acc[2][4];
    #pragma unroll
    for (int i = 0; i < 2; i++)
        #pragma unroll
        for (int j = 0; j < 4; j++) acc[i][j] = 0.f;
    for (int k0 = 0; k0 < K; k0 += 16) {
        if (t < 128) {
            int row = t >> 2, kq = t & 3;
            float4 v = *(const float4*)(A + (size_t)(m0+row)*K + k0 + kq*4);
            As[kq*4+0][row] = v.x; As[kq*4+1][row] = v.y;
            As[kq*4+2][row] = v.z; As[kq*4+3][row] = v.w;
        }
        {
            int kk = t >> 4, nq = t & 15;
            *(float4*)&Bs[kk][nq*4] =
                *(const float4*)(Bm + (size_t)(k0+kk)*N + n0 + nq*4);
        }
        __syncthreads();
        #pragma unroll
        for (int kk = 0; kk < 16; kk++) {
            float a0 = As[kk][ty], a1 = As[kk][ty + 16];
            float b[4];
            #pragma unroll
            for (int j = 0; j < 4; j++) b[j] = Bs[kk][tx + j*16];
            #pragma unroll
            for (int j = 0; j < 4; j++) {
                acc[0][j] += a0 * b[j];
                acc[1][j] += a1 * b[j];
            }
        }
        __syncthreads();
    }
    #pragma unroll
    for (int i = 0; i < 2; i++) {
        int m = m0 + ty + i*16;
        #pragma unroll
        for (int j = 0; j < 4; j++) {
            int n = n0 + tx + j*16;
            float v = acc[i][j] + bias[n];
            if (RELU) v = fmaxf(v, 0.f);
            C[(size_t)m*N + n] = v;
        }
    }
}

// per-row: log_softmax stats, entropy, critic value, gumbel-argmax sample
__global__ __launch_bounds__(256) void k_final(
    const float* __restrict__ Wc, const float* __restrict__ bc,
    float* __restrict__ out) {
    int b_ = blockIdx.x;
    int t = threadIdx.x;
    __shared__ float sred[256];
    __shared__ float sgv[256];
    __shared__ int   sgi[256];
    const float* lrow = g_logits + (size_t)b_ * N_ACT;
    float l[4];
    #pragma unroll
    for (int k = 0; k < 4; k++) l[k] = lrow[t + k*256];

    float mx = fmaxf(fmaxf(l[0], l[1]), fmaxf(l[2], l[3]));
    sred[t] = mx; __syncthreads();
    for (int s = 128; s > 0; s >>= 1) {
        if (t < s) sred[t] = fmaxf(sred[t], sred[t+s]);
        __syncthreads();
    }
    mx = sred[0]; __syncthreads();

    float se = 0.f;
    #pragma unroll
    for (int k = 0; k < 4; k++) se += expf(l[k] - mx);
    sred[t] = se; __syncthreads();
    for (int s = 128; s > 0; s >>= 1) {
        if (t < s) sred[t] += sred[t+s];
        __syncthreads();
    }
    float lse = mx + logf(sred[0]); __syncthreads();

    float ent = 0.f;
    #pragma unroll
    for (int k = 0; k < 4; k++) {
        float lp = l[k] - lse;
        ent += expf(lp) * lp;
    }
    sred[t] = ent; __syncthreads();
    for (int s = 128; s > 0; s >>= 1) {
        if (t < s) sred[t] += sred[t+s];
        __syncthreads();
    }
    float entropy = -sred[0]; __syncthreads();

    const float* ha = g_ha + (size_t)b_ * A2C_H;
    float v = ha[t] * Wc[t] + ha[t + 256] * Wc[t + 256];
    sred[t] = v; __syncthreads();
    for (int s = 128; s > 0; s >>= 1) {
        if (t < s) sred[t] += sred[t+s];
        __syncthreads();
    }
    float vt = sred[0] + bc[0];

    float bv = -3.0e38f; int bn = 0;
    #pragma unroll
    for (int k = 0; k < 4; k++) {
        int n = t + k*256;
        float g = gumbel_at(b_ * N_ACT + n);
        float cand = (l[k] - lse) + g;
        if (cand > bv) { bv = cand; bn = n; }
    }
    sgv[t] = bv; sgi[t] = bn; __syncthreads();
    for (int s = 128; s > 0; s >>= 1) {
        if (t < s) {
            if (sgv[t+s] > sgv[t] || (sgv[t+s] == sgv[t] && sgi[t+s] < sgi[t])) {
                sgv[t] = sgv[t+s]; sgi[t] = sgi[t+s];
            }
        }
        __syncthreads();
    }
    if (t == 0) {
        int nbest = sgi[0];
        out[OFF_A + b_] = (float)nbest;
        out[OFF_PROB + b_] = lrow[nbest] - lse;
        out[OFF_V + b_] = vt;
        out[OFF_ENT + b_] = entropy;
    }
}

extern "C" void kernel_launch(void* const* d_in, const int* in_sizes, int n_in,
                              void* d_out, int out_size) {
    const float* obs     = (const float*)d_in[0];
    const float* barcode = (const float*)d_in[1];
    const float* h_in    = (const float*)d_in[2];
    const float* c_in    = (const float*)d_in[3];
    const int*   widx    = (const int*)  d_in[4];
    const float* Wi      = (const float*)d_in[5];
    const float* bi      = (const float*)d_in[6];
    const float* Wh      = (const float*)d_in[7];
    const float* bh      = (const float*)d_in[8];
    const float* mk      = (const float*)d_in[9];
    const float* mv      = (const float*)d_in[10];
    const float* Wa      = (const float*)d_in[11];
    const float* ba      = (const float*)d_in[12];
    const float* Wact    = (const float*)d_in[13];
    const float* bact    = (const float*)d_in[14];
    const float* Wc      = (const float*)d_in[15];
    const float* bc      = (const float*)d_in[16];
    float* out = (float*)d_out;

    float* g_ha_ptr; cudaGetSymbolAddress((void**)&g_ha_ptr, g_ha);
    float* g_logits_ptr; cudaGetSymbolAddress((void**)&g_logits_ptr, g_logits);

    static int initd = 0;
    if (!initd) {
        cudaFuncSetAttribute(k_mega, cudaFuncAttributeMaxDynamicSharedMemorySize,
                             SIMS_SMEM);
        initd = 1;
    }

    // single stream — mega owns the whole chip anyway (full RF/SM)
    k_qprep<<<BB, 128>>>(barcode);                                        // #1
    k_asplit<<<BB*KTOT/256, 256>>>(obs, h_in);                            // #2
    k_wtrans<<<dim3(KTOT/64, FIVE_H/64), 256>>>(Wi, Wh);                  // #3
    k_mega<<<288, 512, SIMS_SMEM>>>(mk, mv, out + OFF_NK, out + OFF_NV,
                                    bi, bh);                              // #4 (profiled)
    k_lstm<<<BB, 256>>>(c_in, mv, widx, barcode, out);                    // #5
    // ha = relu(c_t @ Wa + ba)
    k_gemm32<1><<<dim3(A2C_H/64, BB/32), 256>>>(out + OFF_C, Wa, ba, g_ha_ptr,
                                                BB, A2C_H, H);            // #6
    // logits = ha @ W_actor + b_actor
    k_gemm32<0><<<dim3(N_ACT/64, BB/32), 256>>>(g_ha_ptr, Wact, bact, g_logits_ptr,
                                                BB, N_ACT, A2C_H);        // #7
    k_final<<<BB, 256>>>(Wc, bc, out);                                    // #8
}

// round 15
// speedup vs baseline: 1.1820x; 1.0488x over previous
#include <cuda_runtime.h>
#include <cuda_bf16.h>
#include <math.h>
#include <stdint.h>

#define H       1024
#define DIN     2048
#define KEY_DIM 1024
#define DICT_LEN 16384
#define A2C_H   512
#define N_ACT   1024
#define BB      256
#define FIVE_H  (5*H)
#define KTOT    3072
#define EPSN    1e-8f

// ---- output layout (float32, tuple order flattened) ----
#define OFF_A    0
#define OFF_PROB 256
#define OFF_V    512
#define OFF_ENT  768
#define OFF_H    1024
#define OFF_C    (OFF_H + BB*H)
#define OFF_BEST (OFF_C + BB*H)
#define OFF_NK   (OFF_BEST + 256)
#define OFF_NV   (OFF_NK + DICT_LEN*KEY_DIM)

// ---- scratch (static device globals; no allocation allowed) ----
__device__ float g_preact[BB*FIVE_H];
__device__ float g_qinv[BB];
__device__ __nv_bfloat16 g_qhi[BB*KEY_DIM];
__device__ __nv_bfloat16 g_qlo[BB*KEY_DIM];
__device__ __nv_bfloat16 g_ahi[BB*KTOT];
__device__ __nv_bfloat16 g_alo[BB*KTOT];
__device__ __nv_bfloat16 g_wthi[(size_t)FIVE_H*KTOT];
__device__ __nv_bfloat16 g_wtlo[(size_t)FIVE_H*KTOT];
__device__ unsigned long long g_ppack[128 * BB];  // [chunk][query]
__device__ float g_ha[BB*A2C_H];
__device__ float g_logits[BB*N_ACT];

__device__ __forceinline__ float sigmoidf_(float x) { return 1.0f / (1.0f + expf(-x)); }

__device__ __forceinline__ unsigned float_flip(float f) {
    unsigned u = __float_as_uint(f);
    return (u & 0x80000000u) ? ~u : (u | 0x80000000u);
}

__device__ __forceinline__ unsigned long long pack_vi(float v, int row) {
    return ((unsigned long long)float_flip(v) << 32) |
           (unsigned)(0x7FFFFFFFu - (unsigned)row);
}

// HMMA m16n8k16 bf16, fp32 accum
__device__ __forceinline__ void mma_bf16(float* c, const uint32_t* a,
                                         uint32_t b0, uint32_t b1) {
    asm volatile(
        "mma.sync.aligned.m16n8k16.row.col.f32.bf16.bf16.f32 "
        "{%0,%1,%2,%3}, {%4,%5,%6,%7}, {%8,%9}, {%0,%1,%2,%3};\n"
        : "+f"(c[0]), "+f"(c[1]), "+f"(c[2]), "+f"(c[3])
        : "r"(a[0]), "r"(a[1]), "r"(a[2]), "r"(a[3]), "r"(b0), "r"(b1));
}

// ldmatrix x4 (b16 8x8 tiles)
__device__ __forceinline__ void ldsm_x4(uint32_t& r0, uint32_t& r1,
                                        uint32_t& r2, uint32_t& r3, uint32_t a) {
    asm volatile("ldmatrix.sync.aligned.m8n8.x4.shared.b16 {%0,%1,%2,%3}, [%4];"
        : "=r"(r0), "=r"(r1), "=r"(r2), "=r"(r3) : "r"(a));
}

__device__ __forceinline__ void split_bf16(float v, __nv_bfloat16& hi, __nv_bfloat16& lo) {
    hi = __float2bfloat16(v);
    lo = __float2bfloat16(v - __bfloat162float(hi));
}

__device__ __forceinline__ unsigned pack_bf2(__nv_bfloat16 a, __nv_bfloat16 b) {
    __nv_bfloat162 t(a, b);
    return *reinterpret_cast<unsigned*>(&t);
}

__device__ __forceinline__ uint32_t smem_u32(const void* p) {
    uint32_t a;
    asm("{ .reg .u64 t; cvta.to.shared.u64 t, %1; cvt.u32.u64 %0, t; }"
        : "=r"(a) : "l"(p));
    return a;
}

__device__ __forceinline__ void cp16(uint32_t s, const void* g) {
    asm volatile("cp.async.cg.shared.global [%0], [%1], 16;" :: "r"(s), "l"(g));
}
#define CP_COMMIT() asm volatile("cp.async.commit_group;" ::: "memory")
#define CP_WAIT0()  asm volatile("cp.async.wait_group 0;" ::: "memory")

// ---- Threefry-2x32-20 with key (0,1)  (jax.random.key(1)) ----
__device__ __forceinline__ void threefry01(unsigned x0, unsigned x1,
                                           unsigned &o0, unsigned &o1) {
    const unsigned ks0 = 0u, ks1 = 1u, ks2 = 0u ^ 1u ^ 0x1BD11BDAu;
    x0 += ks0; x1 += ks1;
#define ROTL(v,r) (((v) << (r)) | ((v) >> (32 - (r))))
#define RND(r) { x0 += x1; x1 = ROTL(x1, r); x1 ^= x0; }
    RND(13) RND(15) RND(26) RND(6)
    x0 += ks1; x1 += ks2 + 1u;
    RND(17) RND(29) RND(16) RND(24)
    x0 += ks2; x1 += ks0 + 2u;
    RND(13) RND(15) RND(26) RND(6)
    x0 += ks0; x1 += ks1 + 3u;
    RND(17) RND(29) RND(16) RND(24)
    x0 += ks1; x1 += ks2 + 4u;
    RND(13) RND(15) RND(26) RND(6)
    x0 += ks2; x1 += ks0 + 5u;
#undef RND
#undef ROTL
    o0 = x0; o1 = x1;
}

// partitionable threefry: counter (0, j), lanes XOR'd
__device__ __forceinline__ float gumbel_at(int j) {
    unsigned o0, o1;
    threefry01(0u, (unsigned)j, o0, o1);
    unsigned bits = o0 ^ o1;
    float f = __uint_as_float((bits >> 9) | 0x3f800000u) - 1.0f;
    const float TINY = 1.1754943508222875e-38f;
    float u = fmaxf(TINY, f * (1.0f - TINY) + TINY);
    return -logf(-logf(u));
}

// ================= kernels =================

// merged prep: qprep (256 blocks) | asplit (3072) | wtrans (3840)
__global__ __launch_bounds__(256) void k_prep(
    const float* __restrict__ q,
    const float* __restrict__ obs, const float* __restrict__ hin,
    const float* __restrict__ Wi, const float* __restrict__ Wh) {
    int bid = blockIdx.x;
    int t = threadIdx.x;
    if (bid < 256) {
        // ---- qprep: row inv-norm + bf16 split (one float4 per thread) ----
        int row = bid;
        float4 v = *(const float4*)(q + (size_t)row * KEY_DIM + t*4);
        float ss = v.x*v.x + v.y*v.y + v.z*v.z + v.w*v.w;
        __nv_bfloat16 h0,h1,h2,h3,l0,l1,l2,l3;
        split_bf16(v.x,h0,l0); split_bf16(v.y,h1,l1);
        split_bf16(v.z,h2,l2); split_bf16(v.w,h3,l3);
        size_t o = (size_t)row*KEY_DIM + t*4;
        *(uint2*)(g_qhi + o) = make_uint2(pack_bf2(h0,h1), pack_bf2(h2,h3));
        *(uint2*)(g_qlo + o) = make_uint2(pack_bf2(l0,l1), pack_bf2(l2,l3));
        #pragma unroll
        for (int os = 16; os > 0; os >>= 1) ss += __shfl_down_sync(0xffffffffu, ss, os);
        __shared__ float w[8];
        if ((t & 31) == 0) w[t >> 5] = ss;
        __syncthreads();
        if (t == 0) {
            float s = 0.f;
            #pragma unroll
            for (int i = 0; i < 8; i++) s += w[i];
            g_qinv[row] = 1.0f / fmaxf(sqrtf(s), EPSN);
        }
    } else if (bid < 256 + 3072) {
        // ---- asplit ----
        int idx = (bid - 256) * 256 + t;
        int m = idx / KTOT;
        int k = idx - m * KTOT;
        float v = (k < DIN) ? obs[(size_t)m*DIN + k] : hin[(size_t)m*H + (k - DIN)];
        __nv_bfloat16 hi, lo;
        split_bf16(v, hi, lo);
        g_ahi[idx] = hi;
        g_alo[idx] = lo;
    } else {
        // ---- wtrans: 64x64 tile, uint4 writes ----
        int pb = bid - 256 - 3072;           // 0..3839
        int k0 = (pb % 48) * 64, n0 = (pb / 48) * 64;
        __shared__ float tile[64][65];
        #pragma unroll
        for (int i = 0; i < 4; i++) {
            int u = t + i*256;
            int row = u >> 4, c4 = u & 15;
            int k = k0 + row;
            const float* src = (k < DIN) ? (Wi + (size_t)k*FIVE_H + n0 + c4*4)
                                         : (Wh + (size_t)(k - DIN)*FIVE_H + n0 + c4*4);
            float4 v = *(const float4*)src;
            tile[row][c4*4+0] = v.x; tile[row][c4*4+1] = v.y;
            tile[row][c4*4+2] = v.z; tile[row][c4*4+3] = v.w;
        }
        __syncthreads();
        #pragma unroll
        for (int i = 0; i < 2; i++) {
            int u = t + i*256;
            int n = u >> 3, oct = u & 7;
            __nv_bfloat16 hv[8], lv[8];
            #pragma unroll
            for (int j = 0; j < 8; j++)
                split_bf16(tile[oct*8 + j][n], hv[j], lv[j]);
            uint4 ph, pl;
            ph.x = pack_bf2(hv[0], hv[1]); ph.y = pack_bf2(hv[2], hv[3]);
            ph.z = pack_bf2(hv[4], hv[5]); ph.w = pack_bf2(hv[6], hv[7]);
            pl.x = pack_bf2(lv[0], lv[1]); pl.y = pack_bf2(lv[2], lv[3]);
            pl.z = pack_bf2(lv[4], lv[5]); pl.w = pack_bf2(lv[6], lv[7]);
            *(uint4*)(g_wthi + (size_t)(n0+n)*KTOT + k0 + oct*8) = ph;
            *(uint4*)(g_wtlo + (size_t)(n0+n)*KTOT + k0 + oct*8) = pl;
        }
    }
}

#define PPITCH 40   // bf16 elements per smem row (80 bytes)
#define SIMS_SBUF 61440
#define SIMS_SMEM (3584 + 2*SIMS_SBUF)

// ---- sims role: CTA 128 keys x 256 queries, 512 thr; fused dict copies ----
__device__ __forceinline__ void sims_body(char* dsm, const float* __restrict__ mk,
                                          const float* __restrict__ mv,
                                          float* __restrict__ nk,
                                          float* __restrict__ nv, int bid) {
    float* sq = (float*)dsm;
    unsigned long long* sbest = (unsigned long long*)(dsm + 1024);
    float* skin = (float*)(dsm + 3072);
    uint32_t sb32 = smem_u32(dsm);
    int tid = threadIdx.x;
    int lane = tid & 31, wid = tid >> 5;
    int g = lane >> 2, t2 = (lane & 3) * 2;
    int wm = wid >> 2, wn = wid & 3;          // 4 x 4 warps, tile 32x64
    int r0 = bid * 128;
    int lrow16 = lane & 15, lk8 = (lane >> 4) * 8;            // A tiles
    int brow8 = lane & 7, bk8 = ((lane >> 3) & 1) * 8, bn8 = (lane >> 4) * 8; // B tiles

    if (tid < 256) { sq[tid] = g_qinv[tid]; sbest[tid] = 0ull; }

    int arow[2], akq[2];
    #pragma unroll
    for (int i = 0; i < 2; i++) { int u = tid + i*512; arow[i] = u >> 3; akq[i] = u & 7; }

    float acc[2][8][4];
    #pragma unroll
    for (int a = 0; a < 2; a++)
        #pragma unroll
        for (int b = 0; b < 8; b++)
            #pragma unroll
            for (int c = 0; c < 4; c++) acc[a][b][c] = 0.f;

    auto issueB = [&](int c, uint32_t bufo) {
        #pragma unroll
        for (int i = 0; i < 2; i++) {
            int u = tid + i*512;
            int row = u >> 2, un = u & 3;
            uint32_t so = bufo + 20480 + row*80 + un*16;      // Bh
            cp16(sb32 + so, g_qhi + (size_t)row*KEY_DIM + c*32 + un*8);
            cp16(sb32 + so + 20480, g_qlo + (size_t)row*KEY_DIM + c*32 + un*8);
        }
    };

    float4 ra[2];
    float ss[2] = {0.f, 0.f};
    #pragma unroll
    for (int i = 0; i < 2; i++)
        ra[i] = *(const float4*)(mk + (size_t)(r0+arow[i])*KEY_DIM + akq[i]*4);
    issueB(0, 3584);
    CP_COMMIT();

    for (int c = 0; c < 32; c++) {
        int b = c & 1;
        uint32_t bufo = 3584 + b*SIMS_SBUF;
        char* smA = dsm + bufo;
        float4 rn[2];
        if (c + 1 < 32) {
            #pragma unroll
            for (int i = 0; i < 2; i++)
                rn[i] = *(const float4*)(mk + (size_t)(r0+arow[i])*KEY_DIM
                                         + (c+1)*32 + akq[i]*4);
        }
        #pragma unroll
        for (int i = 0; i < 2; i++) {
            float4 v = ra[i];
            // fused dict-key copy: same data, coalesced STG.128
            *(float4*)(nk + (size_t)(r0+arow[i])*KEY_DIM + c*32 + akq[i]*4) = v;
            ss[i] += v.x*v.x + v.y*v.y + v.z*v.z + v.w*v.w;
            __nv_bfloat16 h0,h1,h2,h3,l0,l1,l2,l3;
            split_bf16(v.x,h0,l0); split_bf16(v.y,h1,l1);
            split_bf16(v.z,h2,l2); split_bf16(v.w,h3,l3);
            uint2 ph = make_uint2(pack_bf2(h0,h1), pack_bf2(h2,h3));
            uint2 pl = make_uint2(pack_bf2(l0,l1), pack_bf2(l2,l3));
            *(uint2*)(smA + arow[i]*80 + akq[i]*8) = ph;
            *(uint2*)(smA + 10240 + arow[i]*80 + akq[i]*8) = pl;
        }
        CP_WAIT0();
        __syncthreads();
        if (c + 1 < 32) {
            issueB(c+1, 3584 + (1-b)*SIMS_SBUF);
            CP_COMMIT();
        }
        #pragma unroll
        for (int ks = 0; ks < 2; ks++) {
            uint32_t ah[2][4], al[2][4];
            #pragma unroll
            for (int mt = 0; mt < 2; mt++) {
                uint32_t addr = sb32 + bufo +
                    (uint32_t)(((wm*32 + mt*16 + lrow16)*PPITCH + ks*16 + lk8)*2);
                ldsm_x4(ah[mt][0], ah[mt][1], ah[mt][2], ah[mt][3], addr);
                ldsm_x4(al[mt][0], al[mt][1], al[mt][2], al[mt][3], addr + 10240);
            }
            #pragma unroll
            for (int p = 0; p < 4; p++) {
                uint32_t baddr = sb32 + bufo + 20480 +
                    (uint32_t)(((wn*64 + p*16 + bn8 + brow8)*PPITCH + ks*16 + bk8)*2);
                uint32_t bh[4], bl[4];
                ldsm_x4(bh[0], bh[1], bh[2], bh[3], baddr);
                ldsm_x4(bl[0], bl[1], bl[2], bl[3], baddr + 20480);
                #pragma unroll
                for (int mt = 0; mt < 2; mt++) {
                    mma_bf16(acc[mt][2*p],   ah[mt], bh[0], bh[1]);
                    mma_bf16(acc[mt][2*p],   ah[mt], bl[0], bl[1]);
                    mma_bf16(acc[mt][2*p],   al[mt], bh[0], bh[1]);
                    mma_bf16(acc[mt][2*p+1], ah[mt], bh[2], bh[3]);
                    mma_bf16(acc[mt][2*p+1], ah[mt], bl[2], bl[3]);
                    mma_bf16(acc[mt][2*p+1], al[mt], bh[2], bh[3]);
                }
            }
        }
        if (c + 1 < 32) { ra[0] = rn[0]; ra[1] = rn[1]; }
    }

    #pragma unroll
    for (int i = 0; i < 2; i++) {
        float s = ss[i];
        #pragma unroll
        for (int o = 4; o > 0; o >>= 1) s += __shfl_down_sync(0xffffffffu, s, o, 8);
        if ((tid & 7) == 0) skin[arow[i]] = 1.0f / fmaxf(sqrtf(s), EPSN);
    }
    __syncthreads();

    float kin[2][2];
    #pragma unroll
    for (int mt = 0; mt < 2; mt++) {
        int r_ = wm*32 + mt*16 + g;
        kin[mt][0] = skin[r_];
        kin[mt][1] = skin[r_ + 8];
    }
    #pragma unroll
    for (int j = 0; j < 8; j++) {
        int c_ = wn*64 + j*8 + t2;
        float q0 = sq[c_], q1 = sq[c_ + 1];
        unsigned long long m0p = 0ull, m1p = 0ull;
        #pragma unroll
        for (int mt = 0; mt < 2; mt++) {
            int r_ = r0 + wm*32 + mt*16 + g;
            unsigned long long p;
            p = pack_vi(acc[mt][j][0] * kin[mt][0] * q0, r_);     if (p > m0p) m0p = p;
            p = pack_vi(acc[mt][j][2] * kin[mt][1] * q0, r_ + 8); if (p > m0p) m0p = p;
            p = pack_vi(acc[mt][j][1] * kin[mt][0] * q1, r_);     if (p > m1p) m1p = p;
            p = pack_vi(acc[mt][j][3] * kin[mt][1] * q1, r_ + 8); if (p > m1p) m1p = p;
        }
        atomicMax(&sbest[c_], m0p);
        atomicMax(&sbest[c_ + 1], m1p);
    }
    __syncthreads();
    if (tid < 256)
        g_ppack[(size_t)bid * BB + tid] = sbest[tid];

    // fused dict-val copy: this CTA's 128 mem_vals rows -> new_vals (512 KB)
    {
        const float4* src = (const float4*)(mv + (size_t)r0 * H);
        float4* dst = (float4*)(nv + (size_t)r0 * H);
        #pragma unroll 4
        for (int i = tid; i < 128*H/4; i += 512) dst[i] = src[i];
    }
}

// ---- preact role: CTA 64x128 tile of [256 x 5120], 16 warps (2x8) ----
__device__ __forceinline__ void preact_body(char* dsm,
                                            const float* __restrict__ bi,
                                            const float* __restrict__ bh,
                                            int pb) {
    uint32_t sb32 = smem_u32(dsm);
    int tid = threadIdx.x;
    int lane = tid & 31, wid = tid >> 5;
    int g = lane >> 2, t2 = (lane & 3) * 2;
    int wm = wid >> 3, wn = wid & 7;          // 2 x 8 warps, warp tile 32x16
    int n0 = (pb % 40) * 128;
    int m0 = (pb / 40) * 64;
    int lrow16 = lane & 15, lk8 = (lane >> 4) * 8;
    int brow8 = lane & 7, bk8 = ((lane >> 3) & 1) * 8, bn8 = (lane >> 4) * 8;

    float acc[2][2][4];
    #pragma unroll
    for (int a = 0; a < 2; a++)
        #pragma unroll
        for (int b = 0; b < 2; b++)
            #pragma unroll
            for (int c = 0; c < 4; c++) acc[a][b][c] = 0.f;

    auto issueAB = [&](int kci, uint32_t bufo) {
        if (tid < 256) {   // A tile 64x32: 64 rows x 4 uint4
            int row = tid >> 2, un = tid & 3;
            size_t src = (size_t)(m0 + row)*KTOT + kci*32 + un*8;
            uint32_t so = bufo + row*80 + un*16;
            cp16(sb32 + so, g_ahi + src);
            cp16(sb32 + so + 5120, g_alo + src);
        }
        {   // B tile 128x32: 128 rows x 4 uint4, all 512 threads
            int row = tid >> 2, un = tid & 3;
            size_t src = (size_t)(n0 + row)*KTOT + kci*32 + un*8;
            uint32_t so = bufo + 10240 + row*80 + un*16;
            cp16(sb32 + so, g_wthi + src);
            cp16(sb32 + so + 10240, g_wtlo + src);
        }
    };

    issueAB(0, 3584);
    CP_COMMIT();

    for (int kci = 0; kci < 96; kci++) {
        int b = kci & 1;
        uint32_t bufo = 3584 + b*SIMS_SBUF;
        CP_WAIT0();
        __syncthreads();
        if (kci + 1 < 96) {
            issueAB(kci + 1, (uint32_t)(3584 + (1-b)*SIMS_SBUF));
            CP_COMMIT();
        }
        #pragma unroll
        for (int ks = 0; ks < 2; ks++) {
            uint32_t ah[2][4], al[2][4];
            #pragma unroll
            for (int mt = 0; mt < 2; mt++) {
                uint32_t addr = sb32 + bufo +
                    (uint32_t)(((wm*32 + mt*16 + lrow16)*PPITCH + ks*16 + lk8)*2);
                ldsm_x4(ah[mt][0], ah[mt][1], ah[mt][2], ah[mt][3], addr);
                ldsm_x4(al[mt][0], al[mt][1], al[mt][2], al[mt][3], addr + 5120);
            }
            {
                uint32_t baddr = sb32 + bufo + 10240 +
                    (uint32_t)(((wn*16 + bn8 + brow8)*PPITCH + ks*16 + bk8)*2);
                uint32_t bhf[4], blf[4];
                ldsm_x4(bhf[0], bhf[1], bhf[2], bhf[3], baddr);
                ldsm_x4(blf[0], blf[1], blf[2], blf[3], baddr + 10240);
                #pragma unroll
                for (int mt = 0; mt < 2; mt++) {
                    mma_bf16(acc[mt][0], ah[mt], bhf[0], bhf[1]);
                    mma_bf16(acc[mt][0], ah[mt], blf[0], blf[1]);
                    mma_bf16(acc[mt][0], al[mt], bhf[0], bhf[1]);
                    mma_bf16(acc[mt][1], ah[mt], bhf[2], bhf[3]);
                    mma_bf16(acc[mt][1], ah[mt], blf[2], blf[3]);
                    mma_bf16(acc[mt][1], al[mt], bhf[2], bhf[3]);
                }
            }
        }
    }
    #pragma unroll
    for (int mt = 0; mt < 2; mt++) {
        int m = m0 + wm*32 + mt*16 + g;
        #pragma unroll
        for (int j = 0; j < 2; j++) {
            int n = n0 + wn*16 + j*8 + t2;
            float b0 = bi[n] + bh[n], b1 = bi[n+1] + bh[n+1];
            *(float2*)(g_preact + (size_t)m*FIVE_H + n) =
                make_float2(acc[mt][j][0] + b0, acc[mt][j][1] + b1);
            *(float2*)(g_preact + (size_t)(m+8)*FIVE_H + n) =
                make_float2(acc[mt][j][2] + b0, acc[mt][j][3] + b1);
        }
    }
}

// ---- mega: 128 sims CTAs (+dict copy) + 160 preact CTAs in one launch ----
__global__ __launch_bounds__(512, 1) void k_mega(
    const float* __restrict__ mk, const float* __restrict__ mv,
    float* __restrict__ nk, float* __restrict__ nv,
    const float* __restrict__ bi, const float* __restrict__ bh) {
    extern __shared__ __align__(16) char dsm[];
    if (blockIdx.x < 128) sims_body(dsm, mk, mv, nk, nv, blockIdx.x);
    else                  preact_body(dsm, bi, bh, blockIdx.x - 128);
}

// fused: per-b argmax + gates + DND readout + h/c + last-write-wins scatter
__global__ __launch_bounds__(256) void k_lstm(
    const float* __restrict__ c_in, const float* __restrict__ mv,
    const int* __restrict__ widx, const float* __restrict__ q,
    float* __restrict__ out) {
    int b_ = blockIdx.x;          // 256 blocks, one per batch row
    int t = threadIdx.x;
    __shared__ unsigned long long s[128];
    __shared__ int sbesti;
    __shared__ int sflag;
    if (t < 128) s[t] = g_ppack[(size_t)t * BB + b_];
    if (t == 0) sflag = 1;
    __syncthreads();
    for (int st = 64; st > 0; st >>= 1) {
        if (t < st) {
            unsigned long long v = s[t + st];
            if (v > s[t]) s[t] = v;
        }
        __syncthreads();
    }
    if (t == 0) {
        int best = (int)(0x7FFFFFFFu - (unsigned)(s[0] & 0xFFFFFFFFull));
        sbesti = best;
        out[OFF_BEST + b_] = (float)best;
    }
    int myidx = widx[b_];
    if (t > b_ && widx[t] == myidx) sflag = 0;   // later duplicate exists
    __syncthreads();
    int best = sbesti;
    const float* p = g_preact + (size_t)b_ * FIVE_H;
    const float* mrow = mv + (size_t)best * H;
    float ct_r[4];
    #pragma unroll
    for (int r = 0; r < 4; r++) {
        int j = t + r*256;
        int idx = b_ * H + j;
        float f  = sigmoidf_(p[j]);
        float it = sigmoidf_(p[H + j]);
        float o  = sigmoidf_(p[2*H + j]);
        float rr = sigmoidf_(p[3*H + j]);
        float cn = tanhf(p[4*H + j]);
        float m  = tanhf(mrow[j]);
        float ct = f * c_in[idx] + it * cn + rr * m;
        float ht = o * tanhf(ct);
        ct_r[r] = ct;
        out[OFF_H + idx] = ht;
        out[OFF_C + idx] = ct;
    }
    // scatter: if this row is the last writer to myidx, write q and c_t
    if (sflag) {
        #pragma unroll
        for (int r = 0; r < 4; r++) {
            int j = t + r*256;
            out[OFF_NK + (size_t)myidx*KEY_DIM + j] = q[(size_t)b_*KEY_DIM + j];
            out[OFF_NV + (size_t)myidx*H + j] = ct_r[r];
        }
    }
}

// 16x64-tile fp32 GEMM: C = act(A[MxK] @ B[KxN] + bias)
template<int RELU>
__global__ __launch_bounds__(256) void k_gemm16(
    const float* __restrict__ A, const float* __restrict__ Bm,
    const float* __restrict__ bias, float* __restrict__ C,
    int M, int N, int K) {
    __shared__ float As[16][16];
    __shared__ float Bs[16][64];
    int n0 = blockIdx.x * 64;
    int m0 = blockIdx.y * 16;
    int t = threadIdx.x;
    int tx = t & 15, ty = t >> 4;     // 16 x 16
    float acc[4] = {0.f, 0.f, 0.f, 0.f};
    for (int k0 = 0; k0 < K; k0 += 16) {
        if (t < 64) {
            int row = t >> 2, kq = t & 3;
            float4 v = *(const float4*)(A + (size_t)(m0+row)*K + k0 + kq*4);
            As[kq*4+0][row] = v.x; As[kq*4+1][row] = v.y;
            As[kq*4+2][row] = v.z; As[kq*4+3][row] = v.w;
        }
        {
            int kk = t >> 4, nq = t & 15;
            *(float4*)&Bs[kk][nq*4] =
                *(const float4*)(Bm + (size_t)(k0+kk)*N + n0 + nq*4);
        }
        __syncthreads();
        #pragma unroll
        for (int kk = 0; kk < 16; kk++) {
            float a0 = As[kk][ty];
            #pragma unroll
            for (int j = 0; j < 4; j++) acc[j] += a0 * Bs[kk][tx + j*16];
        }
        __syncthreads();
    }
    int m = m0 + ty;
    #pragma unroll
    for (int j = 0; j < 4; j++) {
        int n = n0 + tx + j*16;
        float v = acc[j] + bias[n];
        if (RELU) v = fmaxf(v, 0.f);
        C[(size_t)m*N + n] = v;
    }
}

// per-row: log_softmax stats, entropy, critic value, gumbel-argmax sample
__global__ __launch_bounds__(256) void k_final(
    const float* __restrict__ Wc, const float* __restrict__ bc,
    float* __restrict__ out) {
    int b_ = blockIdx.x;
    int t = threadIdx.x;
    __shared__ float sred[256];
    __shared__ float sgv[256];
    __shared__ int   sgi[256];
    const float* lrow = g_logits + (size_t)b_ * N_ACT;
    float l[4];
    #pragma unroll
    for (int k = 0; k < 4; k++) l[k] = lrow[t + k*256];

    float mx = fmaxf(fmaxf(l[0], l[1]), fmaxf(l[2], l[3]));
    sred[t] = mx; __syncthreads();
    for (int s = 128; s > 0; s >>= 1) {
        if (t < s) sred[t] = fmaxf(sred[t], sred[t+s]);
        __syncthreads();
    }
    mx = sred[0]; __syncthreads();

    float se = 0.f;
    #pragma unroll
    for (int k = 0; k < 4; k++) se += expf(l[k] - mx);
    sred[t] = se; __syncthreads();
    for (int s = 128; s > 0; s >>= 1) {
        if (t < s) sred[t] += sred[t+s];
        __syncthreads();
    }
    float lse = mx + logf(sred[0]); __syncthreads();

    float ent = 0.f;
    #pragma unroll
    for (int k = 0; k < 4; k++) {
        float lp = l[k] - lse;
        ent += expf(lp) * lp;
    }
    sred[t] = ent; __syncthreads();
    for (int s = 128; s > 0; s >>= 1) {
        if (t < s) sred[t] += sred[t+s];
        __syncthreads();
    }
    float entropy = -sred[0]; __syncthreads();

    const float* ha = g_ha + (size_t)b_ * A2C_H;
    float v = ha[t] * Wc[t] + ha[t + 256] * Wc[t + 256];
    sred[t] = v; __syncthreads();
    for (int s = 128; s > 0; s >>= 1) {
        if (t < s) sred[t] += sred[t+s];
        __syncthreads();
    }
    float vt = sred[0] + bc[0];

    float bv = -3.0e38f; int bn = 0;
    #pragma unroll
    for (int k = 0; k < 4; k++) {
        int n = t + k*256;
        float g = gumbel_at(b_ * N_ACT + n);
        float cand = (l[k] - lse) + g;
        if (cand > bv) { bv = cand; bn = n; }
    }
    sgv[t] = bv; sgi[t] = bn; __syncthreads();
    for (int s = 128; s > 0; s >>= 1) {
        if (t < s) {
            if (sgv[t+s] > sgv[t] || (sgv[t+s] == sgv[t] && sgi[t+s] < sgi[t])) {
                sgv[t] = sgv[t+s]; sgi[t] = sgi[t+s];
            }
        }
        __syncthreads();
    }
    if (t == 0) {
        int nbest = sgi[0];
        out[OFF_A + b_] = (float)nbest;
        out[OFF_PROB + b_] = lrow[nbest] - lse;
        out[OFF_V + b_] = vt;
        out[OFF_ENT + b_] = entropy;
    }
}

extern "C" void kernel_launch(void* const* d_in, const int* in_sizes, int n_in,
                              void* d_out, int out_size) {
    const float* obs     = (const float*)d_in[0];
    const float* barcode = (const float*)d_in[1];
    const float* h_in    = (const float*)d_in[2];
    const float* c_in    = (const float*)d_in[3];
    const int*   widx    = (const int*)  d_in[4];
    const float* Wi      = (const float*)d_in[5];
    const float* bi      = (const float*)d_in[6];
    const float* Wh      = (const float*)d_in[7];
    const float* bh      = (const float*)d_in[8];
    const float* mk      = (const float*)d_in[9];
    const float* mv      = (const float*)d_in[10];
    const float* Wa      = (const float*)d_in[11];
    const float* ba      = (const float*)d_in[12];
    const float* Wact    = (const float*)d_in[13];
    const float* bact    = (const float*)d_in[14];
    const float* Wc      = (const float*)d_in[15];
    const float* bc      = (const float*)d_in[16];
    float* out = (float*)d_out;

    float* g_ha_ptr; cudaGetSymbolAddress((void**)&g_ha_ptr, g_ha);
    float* g_logits_ptr; cudaGetSymbolAddress((void**)&g_logits_ptr, g_logits);

    static int initd = 0;
    if (!initd) {
        cudaFuncSetAttribute(k_mega, cudaFuncAttributeMaxDynamicSharedMemorySize,
                             SIMS_SMEM);
        initd = 1;
    }

    k_prep<<<256 + 3072 + 3840, 256>>>(barcode, obs, h_in, Wi, Wh);       // #1
    k_mega<<<288, 512, SIMS_SMEM>>>(mk, mv, out + OFF_NK, out + OFF_NV,
                                    bi, bh);                              // #2
    k_lstm<<<BB, 256>>>(c_in, mv, widx, barcode, out);                    // #3
    // ha = relu(c_t @ Wa + ba)
    k_gemm16<1><<<dim3(A2C_H/64, BB/16), 256>>>(out + OFF_C, Wa, ba, g_ha_ptr,
                                                BB, A2C_H, H);            // #4
    // logits = ha @ W_actor + b_actor
    k_gemm16<0><<<dim3(N_ACT/64, BB/16), 256>>>(g_ha_ptr, Wact, bact, g_logits_ptr,
                                                BB, N_ACT, A2C_H);        // #5
    k_final<<<BB, 256>>>(Wc, bc, out);                                    // #6
}

// round 16
// speedup vs baseline: 1.3899x; 1.1759x over previous
#include <cuda_runtime.h>
#include <cuda_bf16.h>
#include <math.h>
#include <stdint.h>

#define H       1024
#define DIN     2048
#define KEY_DIM 1024
#define DICT_LEN 16384
#define A2C_H   512
#define N_ACT   1024
#define BB      256
#define FIVE_H  (5*H)
#define KTOT    3072
#define EPSN    1e-8f

// ---- output layout (float32, tuple order flattened) ----
#define OFF_A    0
#define OFF_PROB 256
#define OFF_V    512
#define OFF_ENT  768
#define OFF_H    1024
#define OFF_C    (OFF_H + BB*H)
#define OFF_BEST (OFF_C + BB*H)
#define OFF_NK   (OFF_BEST + 256)
#define OFF_NV   (OFF_NK + DICT_LEN*KEY_DIM)

// ---- scratch (static device globals; no allocation allowed) ----
__device__ float g_preact[BB*FIVE_H];
__device__ float g_qinv[BB];
__device__ __nv_bfloat16 g_qhi[BB*KEY_DIM];
__device__ __nv_bfloat16 g_qlo[BB*KEY_DIM];
__device__ __nv_bfloat16 g_ahi[BB*KTOT];
__device__ __nv_bfloat16 g_alo[BB*KTOT];
__device__ __nv_bfloat16 g_wthi[(size_t)FIVE_H*KTOT];
__device__ __nv_bfloat16 g_wtlo[(size_t)FIVE_H*KTOT];
__device__ __nv_bfloat16 g_chi[BB*H];
__device__ __nv_bfloat16 g_clo[BB*H];
__device__ __nv_bfloat16 g_wathi[(size_t)A2C_H*H];
__device__ __nv_bfloat16 g_watlo[(size_t)A2C_H*H];
__device__ __nv_bfloat16 g_wacthi[(size_t)N_ACT*A2C_H];
__device__ __nv_bfloat16 g_wactlo[(size_t)N_ACT*A2C_H];
__device__ __nv_bfloat16 g_hahi[BB*A2C_H];
__device__ __nv_bfloat16 g_halo[BB*A2C_H];
__device__ unsigned long long g_ppack[128 * BB];  // [chunk][query]
__device__ float g_ha[BB*A2C_H];
__device__ float g_logits[BB*N_ACT];

__device__ __forceinline__ float sigmoidf_(float x) { return 1.0f / (1.0f + expf(-x)); }

__device__ __forceinline__ unsigned float_flip(float f) {
    unsigned u = __float_as_uint(f);
    return (u & 0x80000000u) ? ~u : (u | 0x80000000u);
}

__device__ __forceinline__ unsigned long long pack_vi(float v, int row) {
    return ((unsigned long long)float_flip(v) << 32) |
           (unsigned)(0x7FFFFFFFu - (unsigned)row);
}

// HMMA m16n8k16 bf16, fp32 accum
__device__ __forceinline__ void mma_bf16(float* c, const uint32_t* a,
                                         uint32_t b0, uint32_t b1) {
    asm volatile(
        "mma.sync.aligned.m16n8k16.row.col.f32.bf16.bf16.f32 "
        "{%0,%1,%2,%3}, {%4,%5,%6,%7}, {%8,%9}, {%0,%1,%2,%3};\n"
        : "+f"(c[0]), "+f"(c[1]), "+f"(c[2]), "+f"(c[3])
        : "r"(a[0]), "r"(a[1]), "r"(a[2]), "r"(a[3]), "r"(b0), "r"(b1));
}

// ldmatrix x4 (b16 8x8 tiles)
__device__ __forceinline__ void ldsm_x4(uint32_t& r0, uint32_t& r1,
                                        uint32_t& r2, uint32_t& r3, uint32_t a) {
    asm volatile("ldmatrix.sync.aligned.m8n8.x4.shared.b16 {%0,%1,%2,%3}, [%4];"
        : "=r"(r0), "=r"(r1), "=r"(r2), "=r"(r3) : "r"(a));
}

__device__ __forceinline__ void split_bf16(float v, __nv_bfloat16& hi, __nv_bfloat16& lo) {
    hi = __float2bfloat16(v);
    lo = __float2bfloat16(v - __bfloat162float(hi));
}

__device__ __forceinline__ unsigned pack_bf2(__nv_bfloat16 a, __nv_bfloat16 b) {
    __nv_bfloat162 t(a, b);
    return *reinterpret_cast<unsigned*>(&t);
}

__device__ __forceinline__ uint32_t smem_u32(const void* p) {
    uint32_t a;
    asm("{ .reg .u64 t; cvta.to.shared.u64 t, %1; cvt.u32.u64 %0, t; }"
        : "=r"(a) : "l"(p));
    return a;
}

__device__ __forceinline__ void cp16(uint32_t s, const void* g) {
    asm volatile("cp.async.cg.shared.global [%0], [%1], 16;" :: "r"(s), "l"(g));
}
#define CP_COMMIT() asm volatile("cp.async.commit_group;" ::: "memory")
#define CP_WAIT0()  asm volatile("cp.async.wait_group 0;" ::: "memory")

// ---- Threefry-2x32-20 with key (0,1)  (jax.random.key(1)) ----
__device__ __forceinline__ void threefry01(unsigned x0, unsigned x1,
                                           unsigned &o0, unsigned &o1) {
    const unsigned ks0 = 0u, ks1 = 1u, ks2 = 0u ^ 1u ^ 0x1BD11BDAu;
    x0 += ks0; x1 += ks1;
#define ROTL(v,r) (((v) << (r)) | ((v) >> (32 - (r))))
#define RND(r) { x0 += x1; x1 = ROTL(x1, r); x1 ^= x0; }
    RND(13) RND(15) RND(26) RND(6)
    x0 += ks1; x1 += ks2 + 1u;
    RND(17) RND(29) RND(16) RND(24)
    x0 += ks2; x1 += ks0 + 2u;
    RND(13) RND(15) RND(26) RND(6)
    x0 += ks0; x1 += ks1 + 3u;
    RND(17) RND(29) RND(16) RND(24)
    x0 += ks1; x1 += ks2 + 4u;
    RND(13) RND(15) RND(26) RND(6)
    x0 += ks2; x1 += ks0 + 5u;
#undef RND
#undef ROTL
    o0 = x0; o1 = x1;
}

// partitionable threefry: counter (0, j), lanes XOR'd
__device__ __forceinline__ float gumbel_at(int j) {
    unsigned o0, o1;
    threefry01(0u, (unsigned)j, o0, o1);
    unsigned bits = o0 ^ o1;
    float f = __uint_as_float((bits >> 9) | 0x3f800000u) - 1.0f;
    const float TINY = 1.1754943508222875e-38f;
    float u = fmaxf(TINY, f * (1.0f - TINY) + TINY);
    return -logf(-logf(u));
}

// ================= kernels =================

// generic 64x64 transpose+split role helper (uses caller's shared tile)
__device__ __forceinline__ void trans_role(
    float (*tile)[65], const float* __restrict__ src, int ldsrc,
    __nv_bfloat16* __restrict__ dsthi, __nv_bfloat16* __restrict__ dstlo,
    int lddst, int k0, int n0, int t) {
    #pragma unroll
    for (int i = 0; i < 4; i++) {
        int u = t + i*256;
        int row = u >> 4, c4 = u & 15;
        float4 v = *(const float4*)(src + (size_t)(k0+row)*ldsrc + n0 + c4*4);
        tile[row][c4*4+0] = v.x; tile[row][c4*4+1] = v.y;
        tile[row][c4*4+2] = v.z; tile[row][c4*4+3] = v.w;
    }
    __syncthreads();
    #pragma unroll
    for (int i = 0; i < 2; i++) {
        int u = t + i*256;
        int n = u >> 3, oct = u & 7;
        __nv_bfloat16 hv[8], lv[8];
        #pragma unroll
        for (int j = 0; j < 8; j++)
            split_bf16(tile[oct*8 + j][n], hv[j], lv[j]);
        uint4 ph, pl;
        ph.x = pack_bf2(hv[0], hv[1]); ph.y = pack_bf2(hv[2], hv[3]);
        ph.z = pack_bf2(hv[4], hv[5]); ph.w = pack_bf2(hv[6], hv[7]);
        pl.x = pack_bf2(lv[0], lv[1]); pl.y = pack_bf2(lv[2], lv[3]);
        pl.z = pack_bf2(lv[4], lv[5]); pl.w = pack_bf2(lv[6], lv[7]);
        *(uint4*)(dsthi + (size_t)(n0+n)*lddst + k0 + oct*8) = ph;
        *(uint4*)(dstlo + (size_t)(n0+n)*lddst + k0 + oct*8) = pl;
    }
}

// merged prep: qprep(256) | asplit(3072) | wtrans(3840) | WaT(128) | WactT(128)
__global__ __launch_bounds__(256) void k_prep(
    const float* __restrict__ q,
    const float* __restrict__ obs, const float* __restrict__ hin,
    const float* __restrict__ Wi, const float* __restrict__ Wh,
    const float* __restrict__ Wa, const float* __restrict__ Wact) {
    __shared__ float tile[64][65];
    int bid = blockIdx.x;
    int t = threadIdx.x;
    if (bid < 256) {
        // ---- qprep: row inv-norm + bf16 split (one float4 per thread) ----
        int row = bid;
        float4 v = *(const float4*)(q + (size_t)row * KEY_DIM + t*4);
        float ss = v.x*v.x + v.y*v.y + v.z*v.z + v.w*v.w;
        __nv_bfloat16 h0,h1,h2,h3,l0,l1,l2,l3;
        split_bf16(v.x,h0,l0); split_bf16(v.y,h1,l1);
        split_bf16(v.z,h2,l2); split_bf16(v.w,h3,l3);
        size_t o = (size_t)row*KEY_DIM + t*4;
        *(uint2*)(g_qhi + o) = make_uint2(pack_bf2(h0,h1), pack_bf2(h2,h3));
        *(uint2*)(g_qlo + o) = make_uint2(pack_bf2(l0,l1), pack_bf2(l2,l3));
        #pragma unroll
        for (int os = 16; os > 0; os >>= 1) ss += __shfl_down_sync(0xffffffffu, ss, os);
        __shared__ float w[8];
        if ((t & 31) == 0) w[t >> 5] = ss;
        __syncthreads();
        if (t == 0) {
            float s = 0.f;
            #pragma unroll
            for (int i = 0; i < 8; i++) s += w[i];
            g_qinv[row] = 1.0f / fmaxf(sqrtf(s), EPSN);
        }
    } else if (bid < 256 + 3072) {
        // ---- asplit ----
        int idx = (bid - 256) * 256 + t;
        int m = idx / KTOT;
        int k = idx - m * KTOT;
        float v = (k < DIN) ? obs[(size_t)m*DIN + k] : hin[(size_t)m*H + (k - DIN)];
        __nv_bfloat16 hi, lo;
        split_bf16(v, hi, lo);
        g_ahi[idx] = hi;
        g_alo[idx] = lo;
    } else if (bid < 256 + 3072 + 3840) {
        // ---- wtrans: W = concat(Wi, Wh), 64x64 tile ----
        int pb = bid - 256 - 3072;
        int k0 = (pb % 48) * 64, n0 = (pb / 48) * 64;
        #pragma unroll
        for (int i = 0; i < 4; i++) {
            int u = t + i*256;
            int row = u >> 4, c4 = u & 15;
            int k = k0 + row;
            const float* src = (k < DIN) ? (Wi + (size_t)k*FIVE_H + n0 + c4*4)
                                         : (Wh + (size_t)(k - DIN)*FIVE_H + n0 + c4*4);
            float4 v = *(const float4*)src;
            tile[row][c4*4+0] = v.x; tile[row][c4*4+1] = v.y;
            tile[row][c4*4+2] = v.z; tile[row][c4*4+3] = v.w;
        }
        __syncthreads();
        #pragma unroll
        for (int i = 0; i < 2; i++) {
            int u = t + i*256;
            int n = u >> 3, oct = u & 7;
            __nv_bfloat16 hv[8], lv[8];
            #pragma unroll
            for (int j = 0; j < 8; j++)
                split_bf16(tile[oct*8 + j][n], hv[j], lv[j]);
            uint4 ph, pl;
            ph.x = pack_bf2(hv[0], hv[1]); ph.y = pack_bf2(hv[2], hv[3]);
            ph.z = pack_bf2(hv[4], hv[5]); ph.w = pack_bf2(hv[6], hv[7]);
            pl.x = pack_bf2(lv[0], lv[1]); pl.y = pack_bf2(lv[2], lv[3]);
            pl.z = pack_bf2(lv[4], lv[5]); pl.w = pack_bf2(lv[6], lv[7]);
            *(uint4*)(g_wthi + (size_t)(n0+n)*KTOT + k0 + oct*8) = ph;
            *(uint4*)(g_wtlo + (size_t)(n0+n)*KTOT + k0 + oct*8) = pl;
        }
    } else if (bid < 256 + 3072 + 3840 + 128) {
        // ---- WaT: Wa [1024][512] -> [512][1024] ----
        int pb = bid - 256 - 3072 - 3840;
        trans_role(tile, Wa, A2C_H, g_wathi, g_watlo, H,
                   (pb % 16) * 64, (pb / 16) * 64, t);
    } else {
        // ---- WactT: Wact [512][1024] -> [1024][512] ----
        int pb = bid - 256 - 3072 - 3840 - 128;
        trans_role(tile, Wact, N_ACT, g_wacthi, g_wactlo, A2C_H,
                   (pb % 8) * 64, (pb / 8) * 64, t);
    }
}

#define PPITCH 40   // bf16 elements per smem row (80 bytes)
#define SIMS_SBUF 61440
#define SIMS_SMEM (3584 + 2*SIMS_SBUF)

// ---- sims role: CTA 128 keys x 256 queries, 512 thr; fused dict copies ----
__device__ __forceinline__ void sims_body(char* dsm, const float* __restrict__ mk,
                                          const float* __restrict__ mv,
                                          float* __restrict__ nk,
                                          float* __restrict__ nv, int bid) {
    float* sq = (float*)dsm;
    unsigned long long* sbest = (unsigned long long*)(dsm + 1024);
    float* skin = (float*)(dsm + 3072);
    uint32_t sb32 = smem_u32(dsm);
    int tid = threadIdx.x;
    int lane = tid & 31, wid = tid >> 5;
    int g = lane >> 2, t2 = (lane & 3) * 2;
    int wm = wid >> 2, wn = wid & 3;          // 4 x 4 warps, tile 32x64
    int r0 = bid * 128;
    int lrow16 = lane & 15, lk8 = (lane >> 4) * 8;
    int brow8 = lane & 7, bk8 = ((lane >> 3) & 1) * 8, bn8 = (lane >> 4) * 8;

    if (tid < 256) { sq[tid] = g_qinv[tid]; sbest[tid] = 0ull; }

    int arow[2], akq[2];
    #pragma unroll
    for (int i = 0; i < 2; i++) { int u = tid + i*512; arow[i] = u >> 3; akq[i] = u & 7; }

    float acc[2][8][4];
    #pragma unroll
    for (int a = 0; a < 2; a++)
        #pragma unroll
        for (int b = 0; b < 8; b++)
            #pragma unroll
            for (int c = 0; c < 4; c++) acc[a][b][c] = 0.f;

    auto issueB = [&](int c, uint32_t bufo) {
        #pragma unroll
        for (int i = 0; i < 2; i++) {
            int u = tid + i*512;
            int row = u >> 2, un = u & 3;
            uint32_t so = bufo + 20480 + row*80 + un*16;      // Bh
            cp16(sb32 + so, g_qhi + (size_t)row*KEY_DIM + c*32 + un*8);
            cp16(sb32 + so + 20480, g_qlo + (size_t)row*KEY_DIM + c*32 + un*8);
        }
    };

    float4 ra[2];
    float ss[2] = {0.f, 0.f};
    #pragma unroll
    for (int i = 0; i < 2; i++)
        ra[i] = *(const float4*)(mk + (size_t)(r0+arow[i])*KEY_DIM + akq[i]*4);
    issueB(0, 3584);
    CP_COMMIT();

    for (int c = 0; c < 32; c++) {
        int b = c & 1;
        uint32_t bufo = 3584 + b*SIMS_SBUF;
        char* smA = dsm + bufo;
        float4 rn[2];
        if (c + 1 < 32) {
            #pragma unroll
            for (int i = 0; i < 2; i++)
                rn[i] = *(const float4*)(mk + (size_t)(r0+arow[i])*KEY_DIM
                                         + (c+1)*32 + akq[i]*4);
        }
        #pragma unroll
        for (int i = 0; i < 2; i++) {
            float4 v = ra[i];
            *(float4*)(nk + (size_t)(r0+arow[i])*KEY_DIM + c*32 + akq[i]*4) = v;
            ss[i] += v.x*v.x + v.y*v.y + v.z*v.z + v.w*v.w;
            __nv_bfloat16 h0,h1,h2,h3,l0,l1,l2,l3;
            split_bf16(v.x,h0,l0); split_bf16(v.y,h1,l1);
            split_bf16(v.z,h2,l2); split_bf16(v.w,h3,l3);
            uint2 ph = make_uint2(pack_bf2(h0,h1), pack_bf2(h2,h3));
            uint2 pl = make_uint2(pack_bf2(l0,l1), pack_bf2(l2,l3));
            *(uint2*)(smA + arow[i]*80 + akq[i]*8) = ph;
            *(uint2*)(smA + 10240 + arow[i]*80 + akq[i]*8) = pl;
        }
        CP_WAIT0();
        __syncthreads();
        if (c + 1 < 32) {
            issueB(c+1, 3584 + (1-b)*SIMS_SBUF);
            CP_COMMIT();
        }
        #pragma unroll
        for (int ks = 0; ks < 2; ks++) {
            uint32_t ah[2][4], al[2][4];
            #pragma unroll
            for (int mt = 0; mt < 2; mt++) {
                uint32_t addr = sb32 + bufo +
                    (uint32_t)(((wm*32 + mt*16 + lrow16)*PPITCH + ks*16 + lk8)*2);
                ldsm_x4(ah[mt][0], ah[mt][1], ah[mt][2], ah[mt][3], addr);
                ldsm_x4(al[mt][0], al[mt][1], al[mt][2], al[mt][3], addr + 10240);
            }
            #pragma unroll
            for (int p = 0; p < 4; p++) {
                uint32_t baddr = sb32 + bufo + 20480 +
                    (uint32_t)(((wn*64 + p*16 + bn8 + brow8)*PPITCH + ks*16 + bk8)*2);
                uint32_t bh[4], bl[4];
                ldsm_x4(bh[0], bh[1], bh[2], bh[3], baddr);
                ldsm_x4(bl[0], bl[1], bl[2], bl[3], baddr + 20480);
                #pragma unroll
                for (int mt = 0; mt < 2; mt++) {
                    mma_bf16(acc[mt][2*p],   ah[mt], bh[0], bh[1]);
                    mma_bf16(acc[mt][2*p],   ah[mt], bl[0], bl[1]);
                    mma_bf16(acc[mt][2*p],   al[mt], bh[0], bh[1]);
                    mma_bf16(acc[mt][2*p+1], ah[mt], bh[2], bh[3]);
                    mma_bf16(acc[mt][2*p+1], ah[mt], bl[2], bl[3]);
                    mma_bf16(acc[mt][2*p+1], al[mt], bh[2], bh[3]);
                }
            }
        }
        if (c + 1 < 32) { ra[0] = rn[0]; ra[1] = rn[1]; }
    }

    #pragma unroll
    for (int i = 0; i < 2; i++) {
        float s = ss[i];
        #pragma unroll
        for (int o = 4; o > 0; o >>= 1) s += __shfl_down_sync(0xffffffffu, s, o, 8);
        if ((tid & 7) == 0) skin[arow[i]] = 1.0f / fmaxf(sqrtf(s), EPSN);
    }
    __syncthreads();

    float kin[2][2];
    #pragma unroll
    for (int mt = 0; mt < 2; mt++) {
        int r_ = wm*32 + mt*16 + g;
        kin[mt][0] = skin[r_];
        kin[mt][1] = skin[r_ + 8];
    }
    #pragma unroll
    for (int j = 0; j < 8; j++) {
        int c_ = wn*64 + j*8 + t2;
        float q0 = sq[c_], q1 = sq[c_ + 1];
        unsigned long long m0p = 0ull, m1p = 0ull;
        #pragma unroll
        for (int mt = 0; mt < 2; mt++) {
            int r_ = r0 + wm*32 + mt*16 + g;
            unsigned long long p;
            p = pack_vi(acc[mt][j][0] * kin[mt][0] * q0, r_);     if (p > m0p) m0p = p;
            p = pack_vi(acc[mt][j][2] * kin[mt][1] * q0, r_ + 8); if (p > m0p) m0p = p;
            p = pack_vi(acc[mt][j][1] * kin[mt][0] * q1, r_);     if (p > m1p) m1p = p;
            p = pack_vi(acc[mt][j][3] * kin[mt][1] * q1, r_ + 8); if (p > m1p) m1p = p;
        }
        atomicMax(&sbest[c_], m0p);
        atomicMax(&sbest[c_ + 1], m1p);
    }
    __syncthreads();
    if (tid < 256)
        g_ppack[(size_t)bid * BB + tid] = sbest[tid];

    // fused dict-val copy
    {
        const float4* src = (const float4*)(mv + (size_t)r0 * H);
        float4* dst = (float4*)(nv + (size_t)r0 * H);
        #pragma unroll 4
        for (int i = tid; i < 128*H/4; i += 512) dst[i] = src[i];
    }
}

// ---- preact role: CTA 64x128 tile of [256 x 5120], 16 warps (2x8) ----
__device__ __forceinline__ void preact_body(char* dsm,
                                            const float* __restrict__ bi,
                                            const float* __restrict__ bh,
                                            int pb) {
    uint32_t sb32 = smem_u32(dsm);
    int tid = threadIdx.x;
    int lane = tid & 31, wid = tid >> 5;
    int g = lane >> 2, t2 = (lane & 3) * 2;
    int wm = wid >> 3, wn = wid & 7;          // 2 x 8 warps, warp tile 32x16
    int n0 = (pb % 40) * 128;
    int m0 = (pb / 40) * 64;
    int lrow16 = lane & 15, lk8 = (lane >> 4) * 8;
    int brow8 = lane & 7, bk8 = ((lane >> 3) & 1) * 8, bn8 = (lane >> 4) * 8;

    float acc[2][2][4];
    #pragma unroll
    for (int a = 0; a < 2; a++)
        #pragma unroll
        for (int b = 0; b < 2; b++)
            #pragma unroll
            for (int c = 0; c < 4; c++) acc[a][b][c] = 0.f;

    auto issueAB = [&](int kci, uint32_t bufo) {
        if (tid < 256) {
            int row = tid >> 2, un = tid & 3;
            size_t src = (size_t)(m0 + row)*KTOT + kci*32 + un*8;
            uint32_t so = bufo + row*80 + un*16;
            cp16(sb32 + so, g_ahi + src);
            cp16(sb32 + so + 5120, g_alo + src);
        }
        {
            int row = tid >> 2, un = tid & 3;
            size_t src = (size_t)(n0 + row)*KTOT + kci*32 + un*8;
            uint32_t so = bufo + 10240 + row*80 + un*16;
            cp16(sb32 + so, g_wthi + src);
            cp16(sb32 + so + 10240, g_wtlo + src);
        }
    };

    issueAB(0, 3584);
    CP_COMMIT();

    for (int kci = 0; kci < 96; kci++) {
        int b = kci & 1;
        uint32_t bufo = 3584 + b*SIMS_SBUF;
        CP_WAIT0();
        __syncthreads();
        if (kci + 1 < 96) {
            issueAB(kci + 1, (uint32_t)(3584 + (1-b)*SIMS_SBUF));
            CP_COMMIT();
        }
        #pragma unroll
        for (int ks = 0; ks < 2; ks++) {
            uint32_t ah[2][4], al[2][4];
            #pragma unroll
            for (int mt = 0; mt < 2; mt++) {
                uint32_t addr = sb32 + bufo +
                    (uint32_t)(((wm*32 + mt*16 + lrow16)*PPITCH + ks*16 + lk8)*2);
                ldsm_x4(ah[mt][0], ah[mt][1], ah[mt][2], ah[mt][3], addr);
                ldsm_x4(al[mt][0], al[mt][1], al[mt][2], al[mt][3], addr + 5120);
            }
            {
                uint32_t baddr = sb32 + bufo + 10240 +
                    (uint32_t)(((wn*16 + bn8 + brow8)*PPITCH + ks*16 + bk8)*2);
                uint32_t bhf[4], blf[4];
                ldsm_x4(bhf[0], bhf[1], bhf[2], bhf[3], baddr);
                ldsm_x4(blf[0], blf[1], blf[2], blf[3], baddr + 10240);
                #pragma unroll
                for (int mt = 0; mt < 2; mt++) {
                    mma_bf16(acc[mt][0], ah[mt], bhf[0], bhf[1]);
                    mma_bf16(acc[mt][0], ah[mt], blf[0], blf[1]);
                    mma_bf16(acc[mt][0], al[mt], bhf[0], bhf[1]);
                    mma_bf16(acc[mt][1], ah[mt], bhf[2], bhf[3]);
                    mma_bf16(acc[mt][1], ah[mt], blf[2], blf[3]);
                    mma_bf16(acc[mt][1], al[mt], bhf[2], bhf[3]);
                }
            }
        }
    }
    #pragma unroll
    for (int mt = 0; mt < 2; mt++) {
        int m = m0 + wm*32 + mt*16 + g;
        #pragma unroll
        for (int j = 0; j < 2; j++) {
            int n = n0 + wn*16 + j*8 + t2;
            float b0 = bi[n] + bh[n], b1 = bi[n+1] + bh[n+1];
            *(float2*)(g_preact + (size_t)m*FIVE_H + n) =
                make_float2(acc[mt][j][0] + b0, acc[mt][j][1] + b1);
            *(float2*)(g_preact + (size_t)(m+8)*FIVE_H + n) =
                make_float2(acc[mt][j][2] + b0, acc[mt][j][3] + b1);
        }
    }
}

// ---- mega: 128 sims CTAs (+dict copy) + 160 preact CTAs in one launch ----
__global__ __launch_bounds__(512, 1) void k_mega(
    const float* __restrict__ mk, const float* __restrict__ mv,
    float* __restrict__ nk, float* __restrict__ nv,
    const float* __restrict__ bi, const float* __restrict__ bh) {
    extern __shared__ __align__(16) char dsm[];
    if (blockIdx.x < 128) sims_body(dsm, mk, mv, nk, nv, blockIdx.x);
    else                  preact_body(dsm, bi, bh, blockIdx.x - 128);
}

// fused: per-b argmax + gates + DND readout + h/c (+bf16 split) + scatter
__global__ __launch_bounds__(256) void k_lstm(
    const float* __restrict__ c_in, const float* __restrict__ mv,
    const int* __restrict__ widx, const float* __restrict__ q,
    float* __restrict__ out) {
    int b_ = blockIdx.x;
    int t = threadIdx.x;
    __shared__ unsigned long long s[128];
    __shared__ int sbesti;
    __shared__ int sflag;
    if (t < 128) s[t] = g_ppack[(size_t)t * BB + b_];
    if (t == 0) sflag = 1;
    __syncthreads();
    for (int st = 64; st > 0; st >>= 1) {
        if (t < st) {
            unsigned long long v = s[t + st];
            if (v > s[t]) s[t] = v;
        }
        __syncthreads();
    }
    if (t == 0) {
        int best = (int)(0x7FFFFFFFu - (unsigned)(s[0] & 0xFFFFFFFFull));
        sbesti = best;
        out[OFF_BEST + b_] = (float)best;
    }
    int myidx = widx[b_];
    if (t > b_ && widx[t] == myidx) sflag = 0;
    __syncthreads();
    int best = sbesti;
    const float* p = g_preact + (size_t)b_ * FIVE_H;
    const float* mrow = mv + (size_t)best * H;
    float ct_r[4];
    #pragma unroll
    for (int r = 0; r < 4; r++) {
        int j = t + r*256;
        int idx = b_ * H + j;
        float f  = sigmoidf_(p[j]);
        float it = sigmoidf_(p[H + j]);
        float o  = sigmoidf_(p[2*H + j]);
        float rr = sigmoidf_(p[3*H + j]);
        float cn = tanhf(p[4*H + j]);
        float m  = tanhf(mrow[j]);
        float ct = f * c_in[idx] + it * cn + rr * m;
        float ht = o * tanhf(ct);
        ct_r[r] = ct;
        out[OFF_H + idx] = ht;
        out[OFF_C + idx] = ct;
        __nv_bfloat16 hi, lo;
        split_bf16(ct, hi, lo);
        g_chi[idx] = hi;
        g_clo[idx] = lo;
    }
    if (sflag) {
        #pragma unroll
        for (int r = 0; r < 4; r++) {
            int j = t + r*256;
            out[OFF_NK + (size_t)myidx*KEY_DIM + j] = q[(size_t)b_*KEY_DIM + j];
            out[OFF_NV + (size_t)myidx*H + j] = ct_r[r];
        }
    }
}

// ---- HMMA tail GEMM: CTA 64x64, 8 warps (2x4), K-chunk 32 ----
// C[M,N] = act(A @ Bt^T + bias); A,Bt split bf16 hi/lo, K-major rows.
// WRITE_SPLIT: apply relu, also write bf16 hi/lo of result.
template<int WRITE_SPLIT>
__global__ __launch_bounds__(256) void k_hgemm(
    const __nv_bfloat16* __restrict__ Ahi, const __nv_bfloat16* __restrict__ Alo,
    const __nv_bfloat16* __restrict__ Bthi, const __nv_bfloat16* __restrict__ Btlo,
    const float* __restrict__ bias, float* __restrict__ C,
    __nv_bfloat16* __restrict__ Chi, __nv_bfloat16* __restrict__ Clo,
    int M, int N, int K) {
    __shared__ __align__(16) char smem[2*20480];
    uint32_t sb32 = smem_u32(smem);
    int tid = threadIdx.x;
    int lane = tid & 31, wid = tid >> 5;
    int g = lane >> 2, t2 = (lane & 3) * 2;
    int wm = wid >> 2, wn = wid & 3;          // 2 x 4 warps, warp tile 32x16
    int n0 = blockIdx.x * 64;
    int m0 = blockIdx.y * 64;
    int lrow16 = lane & 15, lk8 = (lane >> 4) * 8;
    int brow8 = lane & 7, bk8 = ((lane >> 3) & 1) * 8, bn8 = (lane >> 4) * 8;

    float acc[2][2][4];
    #pragma unroll
    for (int a = 0; a < 2; a++)
        #pragma unroll
        for (int b = 0; b < 2; b++)
            #pragma unroll
            for (int c = 0; c < 4; c++) acc[a][b][c] = 0.f;

    auto issue = [&](int kci, uint32_t bufo) {
        int row = tid >> 2, un = tid & 3;     // 64 rows x 4 uint4
        size_t asrc = (size_t)(m0 + row)*K + kci*32 + un*8;
        uint32_t so = bufo + row*80 + un*16;
        cp16(sb32 + so, Ahi + asrc);
        cp16(sb32 + so + 5120, Alo + asrc);
        size_t bsrc = (size_t)(n0 + row)*K + kci*32 + un*8;
        cp16(sb32 + so + 10240, Bthi + bsrc);
        cp16(sb32 + so + 15360, Btlo + bsrc);
    };

    int nch = K / 32;
    issue(0, 0);
    CP_COMMIT();

    for (int kci = 0; kci < nch; kci++) {
        int b = kci & 1;
        uint32_t bufo = (uint32_t)(b * 20480);
        CP_WAIT0();
        __syncthreads();
        if (kci + 1 < nch) {
            issue(kci + 1, (uint32_t)((1-b) * 20480));
            CP_COMMIT();
        }
        #pragma unroll
        for (int ks = 0; ks < 2; ks++) {
            uint32_t ah[2][4], al[2][4];
            #pragma unroll
            for (int mt = 0; mt < 2; mt++) {
                uint32_t addr = sb32 + bufo +
                    (uint32_t)(((wm*32 + mt*16 + lrow16)*PPITCH + ks*16 + lk8)*2);
                ldsm_x4(ah[mt][0], ah[mt][1], ah[mt][2], ah[mt][3], addr);
                ldsm_x4(al[mt][0], al[mt][1], al[mt][2], al[mt][3], addr + 5120);
            }
            {
                uint32_t baddr = sb32 + bufo + 10240 +
                    (uint32_t)(((wn*16 + bn8 + brow8)*PPITCH + ks*16 + bk8)*2);
                uint32_t bhf[4], blf[4];
                ldsm_x4(bhf[0], bhf[1], bhf[2], bhf[3], baddr);
                ldsm_x4(blf[0], blf[1], blf[2], blf[3], baddr + 5120);
                #pragma unroll
                for (int mt = 0; mt < 2; mt++) {
                    mma_bf16(acc[mt][0], ah[mt], bhf[0], bhf[1]);
                    mma_bf16(acc[mt][0], ah[mt], blf[0], blf[1]);
                    mma_bf16(acc[mt][0], al[mt], bhf[0], bhf[1]);
                    mma_bf16(acc[mt][1], ah[mt], bhf[2], bhf[3]);
                    mma_bf16(acc[mt][1], ah[mt], blf[2], blf[3]);
                    mma_bf16(acc[mt][1], al[mt], bhf[2], bhf[3]);
                }
            }
        }
    }
    #pragma unroll
    for (int mt = 0; mt < 2; mt++) {
        #pragma unroll
        for (int j = 0; j < 2; j++) {
            int n = n0 + wn*16 + j*8 + t2;
            float b0 = bias[n], b1 = bias[n+1];
            #pragma unroll
            for (int rh = 0; rh < 2; rh++) {
                int m = m0 + wm*32 + mt*16 + g + rh*8;
                float v0 = acc[mt][j][rh*2+0] + b0;
                float v1 = acc[mt][j][rh*2+1] + b1;
                if (WRITE_SPLIT) { v0 = fmaxf(v0, 0.f); v1 = fmaxf(v1, 0.f); }
                *(float2*)(C + (size_t)m*N + n) = make_float2(v0, v1);
                if (WRITE_SPLIT) {
                    __nv_bfloat16 h0,l0,h1,l1;
                    split_bf16(v0, h0, l0);
                    split_bf16(v1, h1, l1);
                    *(unsigned*)(Chi + (size_t)m*N + n) = pack_bf2(h0, h1);
                    *(unsigned*)(Clo + (size_t)m*N + n) = pack_bf2(l0, l1);
                }
            }
        }
    }
}

// per-row: log_softmax stats, entropy, critic value, gumbel-argmax sample
__global__ __launch_bounds__(256) void k_final(
    const float* __restrict__ Wc, const float* __restrict__ bc,
    float* __restrict__ out) {
    int b_ = blockIdx.x;
    int t = threadIdx.x;
    __shared__ float sred[256];
    __shared__ float sgv[256];
    __shared__ int   sgi[256];
    const float* lrow = g_logits + (size_t)b_ * N_ACT;
    float l[4];
    #pragma unroll
    for (int k = 0; k < 4; k++) l[k] = lrow[t + k*256];

    float mx = fmaxf(fmaxf(l[0], l[1]), fmaxf(l[2], l[3]));
    sred[t] = mx; __syncthreads();
    for (int s = 128; s > 0; s >>= 1) {
        if (t < s) sred[t] = fmaxf(sred[t], sred[t+s]);
        __syncthreads();
    }
    mx = sred[0]; __syncthreads();

    float se = 0.f;
    #pragma unroll
    for (int k = 0; k < 4; k++) se += expf(l[k] - mx);
    sred[t] = se; __syncthreads();
    for (int s = 128; s > 0; s >>= 1) {
        if (t < s) sred[t] += sred[t+s];
        __syncthreads();
    }
    float lse = mx + logf(sred[0]); __syncthreads();

    float ent = 0.f;
    #pragma unroll
    for (int k = 0; k < 4; k++) {
        float lp = l[k] - lse;
        ent += expf(lp) * lp;
    }
    sred[t] = ent; __syncthreads();
    for (int s = 128; s > 0; s >>= 1) {
        if (t < s) sred[t] += sred[t+s];
        __syncthreads();
    }
    float entropy = -sred[0]; __syncthreads();

    const float* ha = g_ha + (size_t)b_ * A2C_H;
    float v = ha[t] * Wc[t] + ha[t + 256] * Wc[t + 256];
    sred[t] = v; __syncthreads();
    for (int s = 128; s > 0; s >>= 1) {
        if (t < s) sred[t] += sred[t+s];
        __syncthreads();
    }
    float vt = sred[0] + bc[0];

    float bv = -3.0e38f; int bn = 0;
    #pragma unroll
    for (int k = 0; k < 4; k++) {
        int n = t + k*256;
        float g = gumbel_at(b_ * N_ACT + n);
        float cand = (l[k] - lse) + g;
        if (cand > bv) { bv = cand; bn = n; }
    }
    sgv[t] = bv; sgi[t] = bn; __syncthreads();
    for (int s = 128; s > 0; s >>= 1) {
        if (t < s) {
            if (sgv[t+s] > sgv[t] || (sgv[t+s] == sgv[t] && sgi[t+s] < sgi[t])) {
                sgv[t] = sgv[t+s]; sgi[t] = sgi[t+s];
            }
        }
        __syncthreads();
    }
    if (t == 0) {
        int nbest = sgi[0];
        out[OFF_A + b_] = (float)nbest;
        out[OFF_PROB + b_] = lrow[nbest] - lse;
        out[OFF_V + b_] = vt;
        out[OFF_ENT + b_] = entropy;
    }
}

extern "C" void kernel_launch(void* const* d_in, const int* in_sizes, int n_in,
                              void* d_out, int out_size) {
    const float* obs     = (const float*)d_in[0];
    const float* barcode = (const float*)d_in[1];
    const float* h_in    = (const float*)d_in[2];
    const float* c_in    = (const float*)d_in[3];
    const int*   widx    = (const int*)  d_in[4];
    const float* Wi      = (const float*)d_in[5];
    const float* bi      = (const float*)d_in[6];
    const float* Wh      = (const float*)d_in[7];
    const float* bh      = (const float*)d_in[8];
    const float* mk      = (const float*)d_in[9];
    const float* mv      = (const float*)d_in[10];
    const float* Wa      = (const float*)d_in[11];
    const float* ba      = (const float*)d_in[12];
    const float* Wact    = (const float*)d_in[13];
    const float* bact    = (const float*)d_in[14];
    const float* Wc      = (const float*)d_in[15];
    const float* bc      = (const float*)d_in[16];
    float* out = (float*)d_out;

    float* g_ha_p; cudaGetSymbolAddress((void**)&g_ha_p, g_ha);
    float* g_logits_p; cudaGetSymbolAddress((void**)&g_logits_p, g_logits);
    __nv_bfloat16 *g_chi_p, *g_clo_p, *g_wathi_p, *g_watlo_p,
                  *g_wacthi_p, *g_wactlo_p, *g_hahi_p, *g_halo_p;
    cudaGetSymbolAddress((void**)&g_chi_p, g_chi);
    cudaGetSymbolAddress((void**)&g_clo_p, g_clo);
    cudaGetSymbolAddress((void**)&g_wathi_p, g_wathi);
    cudaGetSymbolAddress((void**)&g_watlo_p, g_watlo);
    cudaGetSymbolAddress((void**)&g_wacthi_p, g_wacthi);
    cudaGetSymbolAddress((void**)&g_wactlo_p, g_wactlo);
    cudaGetSymbolAddress((void**)&g_hahi_p, g_hahi);
    cudaGetSymbolAddress((void**)&g_halo_p, g_halo);

    static int initd = 0;
    if (!initd) {
        cudaFuncSetAttribute(k_mega, cudaFuncAttributeMaxDynamicSharedMemorySize,
                             SIMS_SMEM);
        initd = 1;
    }

    k_prep<<<256 + 3072 + 3840 + 256, 256>>>(barcode, obs, h_in, Wi, Wh,
                                             Wa, Wact);                   // #1
    k_mega<<<288, 512, SIMS_SMEM>>>(mk, mv, out + OFF_NK, out + OFF_NV,
                                    bi, bh);                              // #2
    k_lstm<<<BB, 256>>>(c_in, mv, widx, barcode, out);                    // #3
    // ha = relu(c_t @ Wa + ba), + bf16 split
    k_hgemm<1><<<dim3(A2C_H/64, BB/64), 256>>>(g_chi_p, g_clo_p,
        g_wathi_p, g_watlo_p, ba, g_ha_p, g_hahi_p, g_halo_p,
        BB, A2C_H, H);                                                    // #4 (profiled)
    // logits = ha @ W_actor + b_actor
    k_hgemm<0><<<dim3(N_ACT/64, BB/64), 256>>>(g_hahi_p, g_halo_p,
        g_wacthi_p, g_wactlo_p, bact, g_logits_p, nullptr, nullptr,
        BB, N_ACT, A2C_H);                                                // #5
    k_final<<<BB, 256>>>(Wc, bc, out);                                    // #6
}

// round 17
// speedup vs baseline: 1.4214x; 1.0226x over previous
#include <cuda_runtime.h>
#include <cuda_bf16.h>
#include <math.h>
#include <stdint.h>

#define H       1024
#define DIN     2048
#define KEY_DIM 1024
#define DICT_LEN 16384
#define A2C_H   512
#define N_ACT   1024
#define BB      256
#define FIVE_H  (5*H)
#define KTOT    3072
#define EPSN    1e-8f

// ---- output layout (float32, tuple order flattened) ----
#define OFF_A    0
#define OFF_PROB 256
#define OFF_V    512
#define OFF_ENT  768
#define OFF_H    1024
#define OFF_C    (OFF_H + BB*H)
#define OFF_BEST (OFF_C + BB*H)
#define OFF_NK   (OFF_BEST + 256)
#define OFF_NV   (OFF_NK + DICT_LEN*KEY_DIM)

// ---- scratch (static device globals; no allocation allowed) ----
__device__ float g_preact[BB*FIVE_H];
__device__ float g_qinv[BB];
__device__ __nv_bfloat16 g_qhi[BB*KEY_DIM];
__device__ __nv_bfloat16 g_qlo[BB*KEY_DIM];
__device__ __nv_bfloat16 g_ahi[BB*KTOT];
__device__ __nv_bfloat16 g_alo[BB*KTOT];
__device__ __nv_bfloat16 g_wthi[(size_t)FIVE_H*KTOT];
__device__ __nv_bfloat16 g_wtlo[(size_t)FIVE_H*KTOT];
__device__ __nv_bfloat16 g_chi[BB*H];
__device__ __nv_bfloat16 g_clo[BB*H];
__device__ __nv_bfloat16 g_wathi[(size_t)A2C_H*H];
__device__ __nv_bfloat16 g_watlo[(size_t)A2C_H*H];
__device__ __nv_bfloat16 g_wacthi[(size_t)N_ACT*A2C_H];
__device__ __nv_bfloat16 g_wactlo[(size_t)N_ACT*A2C_H];
__device__ __nv_bfloat16 g_hahi[BB*A2C_H];
__device__ __nv_bfloat16 g_halo[BB*A2C_H];
__device__ unsigned long long g_ppack[256 * 128];  // [ctab][local query]
__device__ float g_ha[BB*A2C_H];
__device__ float g_logits[BB*N_ACT];

__device__ __forceinline__ float sigmoidf_(float x) { return 1.0f / (1.0f + expf(-x)); }

__device__ __forceinline__ unsigned float_flip(float f) {
    unsigned u = __float_as_uint(f);
    return (u & 0x80000000u) ? ~u : (u | 0x80000000u);
}

__device__ __forceinline__ unsigned long long pack_vi(float v, int row) {
    return ((unsigned long long)float_flip(v) << 32) |
           (unsigned)(0x7FFFFFFFu - (unsigned)row);
}

// HMMA m16n8k16 bf16, fp32 accum
__device__ __forceinline__ void mma_bf16(float* c, const uint32_t* a,
                                         uint32_t b0, uint32_t b1) {
    asm volatile(
        "mma.sync.aligned.m16n8k16.row.col.f32.bf16.bf16.f32 "
        "{%0,%1,%2,%3}, {%4,%5,%6,%7}, {%8,%9}, {%0,%1,%2,%3};\n"
        : "+f"(c[0]), "+f"(c[1]), "+f"(c[2]), "+f"(c[3])
        : "r"(a[0]), "r"(a[1]), "r"(a[2]), "r"(a[3]), "r"(b0), "r"(b1));
}

// ldmatrix x4 (b16 8x8 tiles)
__device__ __forceinline__ void ldsm_x4(uint32_t& r0, uint32_t& r1,
                                        uint32_t& r2, uint32_t& r3, uint32_t a) {
    asm volatile("ldmatrix.sync.aligned.m8n8.x4.shared.b16 {%0,%1,%2,%3}, [%4];"
        : "=r"(r0), "=r"(r1), "=r"(r2), "=r"(r3) : "r"(a));
}

__device__ __forceinline__ void split_bf16(float v, __nv_bfloat16& hi, __nv_bfloat16& lo) {
    hi = __float2bfloat16(v);
    lo = __float2bfloat16(v - __bfloat162float(hi));
}

__device__ __forceinline__ unsigned pack_bf2(__nv_bfloat16 a, __nv_bfloat16 b) {
    __nv_bfloat162 t(a, b);
    return *reinterpret_cast<unsigned*>(&t);
}

__device__ __forceinline__ uint32_t smem_u32(const void* p) {
    uint32_t a;
    asm("{ .reg .u64 t; cvta.to.shared.u64 t, %1; cvt.u32.u64 %0, t; }"
        : "=r"(a) : "l"(p));
    return a;
}

__device__ __forceinline__ void cp16(uint32_t s, const void* g) {
    asm volatile("cp.async.cg.shared.global [%0], [%1], 16;" :: "r"(s), "l"(g));
}
#define CP_COMMIT() asm volatile("cp.async.commit_group;" ::: "memory")
#define CP_WAIT0()  asm volatile("cp.async.wait_group 0;" ::: "memory")

// ---- Threefry-2x32-20 with key (0,1)  (jax.random.key(1)) ----
__device__ __forceinline__ void threefry01(unsigned x0, unsigned x1,
                                           unsigned &o0, unsigned &o1) {
    const unsigned ks0 = 0u, ks1 = 1u, ks2 = 0u ^ 1u ^ 0x1BD11BDAu;
    x0 += ks0; x1 += ks1;
#define ROTL(v,r) (((v) << (r)) | ((v) >> (32 - (r))))
#define RND(r) { x0 += x1; x1 = ROTL(x1, r); x1 ^= x0; }
    RND(13) RND(15) RND(26) RND(6)
    x0 += ks1; x1 += ks2 + 1u;
    RND(17) RND(29) RND(16) RND(24)
    x0 += ks2; x1 += ks0 + 2u;
    RND(13) RND(15) RND(26) RND(6)
    x0 += ks0; x1 += ks1 + 3u;
    RND(17) RND(29) RND(16) RND(24)
    x0 += ks1; x1 += ks2 + 4u;
    RND(13) RND(15) RND(26) RND(6)
    x0 += ks2; x1 += ks0 + 5u;
#undef RND
#undef ROTL
    o0 = x0; o1 = x1;
}

// partitionable threefry: counter (0, j), lanes XOR'd
__device__ __forceinline__ float gumbel_at(int j) {
    unsigned o0, o1;
    threefry01(0u, (unsigned)j, o0, o1);
    unsigned bits = o0 ^ o1;
    float f = __uint_as_float((bits >> 9) | 0x3f800000u) - 1.0f;
    const float TINY = 1.1754943508222875e-38f;
    float u = fmaxf(TINY, f * (1.0f - TINY) + TINY);
    return -logf(-logf(u));
}

// ================= kernels =================

// generic 64x64 transpose+split role helper
__device__ __forceinline__ void trans_role(
    float (*tile)[65], const float* __restrict__ src, int ldsrc,
    __nv_bfloat16* __restrict__ dsthi, __nv_bfloat16* __restrict__ dstlo,
    int lddst, int k0, int n0, int t) {
    #pragma unroll
    for (int i = 0; i < 4; i++) {
        int u = t + i*256;
        int row = u >> 4, c4 = u & 15;
        float4 v = *(const float4*)(src + (size_t)(k0+row)*ldsrc + n0 + c4*4);
        tile[row][c4*4+0] = v.x; tile[row][c4*4+1] = v.y;
        tile[row][c4*4+2] = v.z; tile[row][c4*4+3] = v.w;
    }
    __syncthreads();
    #pragma unroll
    for (int i = 0; i < 2; i++) {
        int u = t + i*256;
        int n = u >> 3, oct = u & 7;
        __nv_bfloat16 hv[8], lv[8];
        #pragma unroll
        for (int j = 0; j < 8; j++)
            split_bf16(tile[oct*8 + j][n], hv[j], lv[j]);
        uint4 ph, pl;
        ph.x = pack_bf2(hv[0], hv[1]); ph.y = pack_bf2(hv[2], hv[3]);
        ph.z = pack_bf2(hv[4], hv[5]); ph.w = pack_bf2(hv[6], hv[7]);
        pl.x = pack_bf2(lv[0], lv[1]); pl.y = pack_bf2(lv[2], lv[3]);
        pl.z = pack_bf2(lv[4], lv[5]); pl.w = pack_bf2(lv[6], lv[7]);
        *(uint4*)(dsthi + (size_t)(n0+n)*lddst + k0 + oct*8) = ph;
        *(uint4*)(dstlo + (size_t)(n0+n)*lddst + k0 + oct*8) = pl;
    }
}

// merged prep: qprep(256) | asplit(3072) | wtrans(3840) | WaT(128) | WactT(128)
__global__ __launch_bounds__(256) void k_prep(
    const float* __restrict__ q,
    const float* __restrict__ obs, const float* __restrict__ hin,
    const float* __restrict__ Wi, const float* __restrict__ Wh,
    const float* __restrict__ Wa, const float* __restrict__ Wact) {
    __shared__ float tile[64][65];
    int bid = blockIdx.x;
    int t = threadIdx.x;
    if (bid < 256) {
        int row = bid;
        float4 v = *(const float4*)(q + (size_t)row * KEY_DIM + t*4);
        float ss = v.x*v.x + v.y*v.y + v.z*v.z + v.w*v.w;
        __nv_bfloat16 h0,h1,h2,h3,l0,l1,l2,l3;
        split_bf16(v.x,h0,l0); split_bf16(v.y,h1,l1);
        split_bf16(v.z,h2,l2); split_bf16(v.w,h3,l3);
        size_t o = (size_t)row*KEY_DIM + t*4;
        *(uint2*)(g_qhi + o) = make_uint2(pack_bf2(h0,h1), pack_bf2(h2,h3));
        *(uint2*)(g_qlo + o) = make_uint2(pack_bf2(l0,l1), pack_bf2(l2,l3));
        #pragma unroll
        for (int os = 16; os > 0; os >>= 1) ss += __shfl_down_sync(0xffffffffu, ss, os);
        __shared__ float w[8];
        if ((t & 31) == 0) w[t >> 5] = ss;
        __syncthreads();
        if (t == 0) {
            float s = 0.f;
            #pragma unroll
            for (int i = 0; i < 8; i++) s += w[i];
            g_qinv[row] = 1.0f / fmaxf(sqrtf(s), EPSN);
        }
    } else if (bid < 256 + 3072) {
        int idx = (bid - 256) * 256 + t;
        int m = idx / KTOT;
        int k = idx - m * KTOT;
        float v = (k < DIN) ? obs[(size_t)m*DIN + k] : hin[(size_t)m*H + (k - DIN)];
        __nv_bfloat16 hi, lo;
        split_bf16(v, hi, lo);
        g_ahi[idx] = hi;
        g_alo[idx] = lo;
    } else if (bid < 256 + 3072 + 3840) {
        int pb = bid - 256 - 3072;
        int k0 = (pb % 48) * 64, n0 = (pb / 48) * 64;
        #pragma unroll
        for (int i = 0; i < 4; i++) {
            int u = t + i*256;
            int row = u >> 4, c4 = u & 15;
            int k = k0 + row;
            const float* src = (k < DIN) ? (Wi + (size_t)k*FIVE_H + n0 + c4*4)
                                         : (Wh + (size_t)(k - DIN)*FIVE_H + n0 + c4*4);
            float4 v = *(const float4*)src;
            tile[row][c4*4+0] = v.x; tile[row][c4*4+1] = v.y;
            tile[row][c4*4+2] = v.z; tile[row][c4*4+3] = v.w;
        }
        __syncthreads();
        #pragma unroll
        for (int i = 0; i < 2; i++) {
            int u = t + i*256;
            int n = u >> 3, oct = u & 7;
            __nv_bfloat16 hv[8], lv[8];
            #pragma unroll
            for (int j = 0; j < 8; j++)
                split_bf16(tile[oct*8 + j][n], hv[j], lv[j]);
            uint4 ph, pl;
            ph.x = pack_bf2(hv[0], hv[1]); ph.y = pack_bf2(hv[2], hv[3]);
            ph.z = pack_bf2(hv[4], hv[5]); ph.w = pack_bf2(hv[6], hv[7]);
            pl.x = pack_bf2(lv[0], lv[1]); pl.y = pack_bf2(lv[2], lv[3]);
            pl.z = pack_bf2(lv[4], lv[5]); pl.w = pack_bf2(lv[6], lv[7]);
            *(uint4*)(g_wthi + (size_t)(n0+n)*KTOT + k0 + oct*8) = ph;
            *(uint4*)(g_wtlo + (size_t)(n0+n)*KTOT + k0 + oct*8) = pl;
        }
    } else if (bid < 256 + 3072 + 3840 + 128) {
        int pb = bid - 256 - 3072 - 3840;
        trans_role(tile, Wa, A2C_H, g_wathi, g_watlo, H,
                   (pb % 16) * 64, (pb / 16) * 64, t);
    } else {
        int pb = bid - 256 - 3072 - 3840 - 128;
        trans_role(tile, Wact, N_ACT, g_wacthi, g_wactlo, A2C_H,
                   (pb % 8) * 64, (pb / 8) * 64, t);
    }
}

#define PPITCH 40   // bf16 elems per smem row (80 bytes), K-chunk 32
// mega smem: sbest[128]u64 @0 | sq[128]f @1024 | skin[128]f @1536 | bufs @2048
#define MEGA_STAGE 40960
#define MEGA_SMEM (2048 + 2*MEGA_STAGE)   // 83968

// ---- sims role: CTA 128 keys x 128 queries, 256 thr, occ 2 ----
__device__ __forceinline__ void sims_body(char* dsm, const float* __restrict__ mk,
                                          const float* __restrict__ mv,
                                          float* __restrict__ nk,
                                          float* __restrict__ nv, int bid) {
    unsigned long long* sbest = (unsigned long long*)dsm;
    float* sq = (float*)(dsm + 1024);
    float* skin = (float*)(dsm + 1536);
    uint32_t sb32 = smem_u32(dsm);
    int tid = threadIdx.x;
    int lane = tid & 31, wid = tid >> 5;
    int g = lane >> 2, t2 = (lane & 3) * 2;
    int wm = wid >> 2, wn = wid & 3;          // 2 x 4 warps, warp tile 64x32
    int r0 = (bid >> 1) * 128;
    int qb = (bid & 1) * 128;
    bool copy_role = (bid & 1) == 0;
    int lrow16 = lane & 15, lk8 = (lane >> 4) * 8;
    int brow8 = lane & 7, bk8 = ((lane >> 3) & 1) * 8, bn8 = (lane >> 4) * 8;

    if (tid < 128) { sq[tid] = g_qinv[qb + tid]; sbest[tid] = 0ull; }

    float acc[4][4][4];
    #pragma unroll
    for (int a = 0; a < 4; a++)
        #pragma unroll
        for (int b = 0; b < 4; b++)
            #pragma unroll
            for (int c = 0; c < 4; c++) acc[a][b][c] = 0.f;

    auto issueB = [&](int c, uint32_t bufo) {
        #pragma unroll
        for (int i = 0; i < 2; i++) {
            int u = tid + i*256;              // 128 rows x 4 uint4
            int row = u >> 2, un = u & 3;
            uint32_t so = bufo + 20480 + row*80 + un*16;
            cp16(sb32 + so, g_qhi + (size_t)(qb+row)*KEY_DIM + c*32 + un*8);
            cp16(sb32 + so + 10240, g_qlo + (size_t)(qb+row)*KEY_DIM + c*32 + un*8);
        }
    };

    float ss[4] = {0.f, 0.f, 0.f, 0.f};
    issueB(0, 2048);
    CP_COMMIT();

    for (int c = 0; c < 32; c++) {
        int b = c & 1;
        uint32_t bufo = 2048 + b*MEGA_STAGE;
        char* smA = dsm + bufo;
        // load+convert A chunk directly (occ-2 hides LDG latency)
        #pragma unroll
        for (int i = 0; i < 4; i++) {
            int u = tid + i*256;              // 128 rows x 8 float4
            int row = u >> 3, kq = u & 7;
            float4 v = *(const float4*)(mk + (size_t)(r0+row)*KEY_DIM + c*32 + kq*4);
            if (copy_role)
                *(float4*)(nk + (size_t)(r0+row)*KEY_DIM + c*32 + kq*4) = v;
            ss[i] += v.x*v.x + v.y*v.y + v.z*v.z + v.w*v.w;
            __nv_bfloat16 h0,h1,h2,h3,l0,l1,l2,l3;
            split_bf16(v.x,h0,l0); split_bf16(v.y,h1,l1);
            split_bf16(v.z,h2,l2); split_bf16(v.w,h3,l3);
            *(uint2*)(smA + row*80 + kq*8) =
                make_uint2(pack_bf2(h0,h1), pack_bf2(h2,h3));
            *(uint2*)(smA + 10240 + row*80 + kq*8) =
                make_uint2(pack_bf2(l0,l1), pack_bf2(l2,l3));
        }
        CP_WAIT0();
        __syncthreads();
        if (c + 1 < 32) {
            issueB(c+1, 2048 + (1-b)*MEGA_STAGE);
            CP_COMMIT();
        }
        #pragma unroll
        for (int ks = 0; ks < 2; ks++) {
            uint32_t ah[4][4], al[4][4];
            #pragma unroll
            for (int mt = 0; mt < 4; mt++) {
                uint32_t addr = sb32 + bufo +
                    (uint32_t)(((wm*64 + mt*16 + lrow16)*PPITCH + ks*16 + lk8)*2);
                ldsm_x4(ah[mt][0], ah[mt][1], ah[mt][2], ah[mt][3], addr);
                ldsm_x4(al[mt][0], al[mt][1], al[mt][2], al[mt][3], addr + 10240);
            }
            #pragma unroll
            for (int p = 0; p < 2; p++) {
                uint32_t baddr = sb32 + bufo + 20480 +
                    (uint32_t)(((wn*32 + p*16 + bn8 + brow8)*PPITCH + ks*16 + bk8)*2);
                uint32_t bh[4], bl[4];
                ldsm_x4(bh[0], bh[1], bh[2], bh[3], baddr);
                ldsm_x4(bl[0], bl[1], bl[2], bl[3], baddr + 10240);
                #pragma unroll
                for (int mt = 0; mt < 4; mt++) {
                    mma_bf16(acc[mt][2*p],   ah[mt], bh[0], bh[1]);
                    mma_bf16(acc[mt][2*p],   ah[mt], bl[0], bl[1]);
                    mma_bf16(acc[mt][2*p],   al[mt], bh[0], bh[1]);
                    mma_bf16(acc[mt][2*p+1], ah[mt], bh[2], bh[3]);
                    mma_bf16(acc[mt][2*p+1], ah[mt], bl[2], bl[3]);
                    mma_bf16(acc[mt][2*p+1], al[mt], bh[2], bh[3]);
                }
            }
        }
        __syncthreads();
    }

    // kinv: 8 lanes share a row
    #pragma unroll
    for (int i = 0; i < 4; i++) {
        float s = ss[i];
        #pragma unroll
        for (int o = 4; o > 0; o >>= 1) s += __shfl_down_sync(0xffffffffu, s, o, 8);
        if ((tid & 7) == 0) skin[(tid + i*256) >> 3] = 1.0f / fmaxf(sqrtf(s), EPSN);
    }
    __syncthreads();

    float kin[4][2];
    #pragma unroll
    for (int mt = 0; mt < 4; mt++) {
        int r_ = wm*64 + mt*16 + g;
        kin[mt][0] = skin[r_];
        kin[mt][1] = skin[r_ + 8];
    }
    #pragma unroll
    for (int j = 0; j < 4; j++) {
        int c_ = wn*32 + j*8 + t2;
        float q0 = sq[c_], q1 = sq[c_ + 1];
        unsigned long long m0p = 0ull, m1p = 0ull;
        #pragma unroll
        for (int mt = 0; mt < 4; mt++) {
            int r_ = r0 + wm*64 + mt*16 + g;
            unsigned long long p;
            p = pack_vi(acc[mt][j][0] * kin[mt][0] * q0, r_);     if (p > m0p) m0p = p;
            p = pack_vi(acc[mt][j][2] * kin[mt][1] * q0, r_ + 8); if (p > m0p) m0p = p;
            p = pack_vi(acc[mt][j][1] * kin[mt][0] * q1, r_);     if (p > m1p) m1p = p;
            p = pack_vi(acc[mt][j][3] * kin[mt][1] * q1, r_ + 8); if (p > m1p) m1p = p;
        }
        atomicMax(&sbest[c_], m0p);
        atomicMax(&sbest[c_ + 1], m1p);
    }
    __syncthreads();
    if (tid < 128)
        g_ppack[(size_t)bid * 128 + tid] = sbest[tid];

    // fused dict-val copy (even CTAs only): 128 mem_vals rows -> new_vals
    if (copy_role) {
        const float4* src = (const float4*)(mv + (size_t)r0 * H);
        float4* dst = (float4*)(nv + (size_t)r0 * H);
        #pragma unroll 4
        for (int i = tid; i < 128*H/4; i += 256) dst[i] = src[i];
    }
}

// ---- preact role: CTA 64x64 tile, 256 thr, occ 2 (hgemm shape) ----
__device__ __forceinline__ void preact_body(char* dsm,
                                            const float* __restrict__ bi,
                                            const float* __restrict__ bh,
                                            int pb) {
    uint32_t sb32 = smem_u32(dsm);
    int tid = threadIdx.x;
    int lane = tid & 31, wid = tid >> 5;
    int g = lane >> 2, t2 = (lane & 3) * 2;
    int wm = wid >> 2, wn = wid & 3;          // 2 x 4 warps, warp tile 32x16
    int n0 = (pb % 80) * 64;
    int m0 = (pb / 80) * 64;
    int lrow16 = lane & 15, lk8 = (lane >> 4) * 8;
    int brow8 = lane & 7, bk8 = ((lane >> 3) & 1) * 8, bn8 = (lane >> 4) * 8;

    float acc[2][2][4];
    #pragma unroll
    for (int a = 0; a < 2; a++)
        #pragma unroll
        for (int b = 0; b < 2; b++)
            #pragma unroll
            for (int c = 0; c < 4; c++) acc[a][b][c] = 0.f;

    auto issueAB = [&](int kci, uint32_t bufo) {
        int row = tid >> 2, un = tid & 3;     // 64 rows x 4 uint4
        size_t asrc = (size_t)(m0 + row)*KTOT + kci*32 + un*8;
        uint32_t so = bufo + row*80 + un*16;
        cp16(sb32 + so, g_ahi + asrc);
        cp16(sb32 + so + 5120, g_alo + asrc);
        size_t bsrc = (size_t)(n0 + row)*KTOT + kci*32 + un*8;
        cp16(sb32 + so + 10240, g_wthi + bsrc);
        cp16(sb32 + so + 15360, g_wtlo + bsrc);
    };

    issueAB(0, 2048);
    CP_COMMIT();

    for (int kci = 0; kci < 96; kci++) {
        int b = kci & 1;
        uint32_t bufo = 2048 + b*MEGA_STAGE;
        CP_WAIT0();
        __syncthreads();
        if (kci + 1 < 96) {
            issueAB(kci + 1, (uint32_t)(2048 + (1-b)*MEGA_STAGE));
            CP_COMMIT();
        }
        #pragma unroll
        for (int ks = 0; ks < 2; ks++) {
            uint32_t ah[2][4], al[2][4];
            #pragma unroll
            for (int mt = 0; mt < 2; mt++) {
                uint32_t addr = sb32 + bufo +
                    (uint32_t)(((wm*32 + mt*16 + lrow16)*PPITCH + ks*16 + lk8)*2);
                ldsm_x4(ah[mt][0], ah[mt][1], ah[mt][2], ah[mt][3], addr);
                ldsm_x4(al[mt][0], al[mt][1], al[mt][2], al[mt][3], addr + 5120);
            }
            {
                uint32_t baddr = sb32 + bufo + 10240 +
                    (uint32_t)(((wn*16 + bn8 + brow8)*PPITCH + ks*16 + bk8)*2);
                uint32_t bhf[4], blf[4];
                ldsm_x4(bhf[0], bhf[1], bhf[2], bhf[3], baddr);
                ldsm_x4(blf[0], blf[1], blf[2], blf[3], baddr + 5120);
                #pragma unroll
                for (int mt = 0; mt < 2; mt++) {
                    mma_bf16(acc[mt][0], ah[mt], bhf[0], bhf[1]);
                    mma_bf16(acc[mt][0], ah[mt], blf[0], blf[1]);
                    mma_bf16(acc[mt][0], al[mt], bhf[0], bhf[1]);
                    mma_bf16(acc[mt][1], ah[mt], bhf[2], bhf[3]);
                    mma_bf16(acc[mt][1], ah[mt], blf[2], blf[3]);
                    mma_bf16(acc[mt][1], al[mt], bhf[2], bhf[3]);
                }
            }
        }
    }
    #pragma unroll
    for (int mt = 0; mt < 2; mt++) {
        int m = m0 + wm*32 + mt*16 + g;
        #pragma unroll
        for (int j = 0; j < 2; j++) {
            int n = n0 + wn*16 + j*8 + t2;
            float b0 = bi[n] + bh[n], b1 = bi[n+1] + bh[n+1];
            *(float2*)(g_preact + (size_t)m*FIVE_H + n) =
                make_float2(acc[mt][j][0] + b0, acc[mt][j][1] + b1);
            *(float2*)(g_preact + (size_t)(m+8)*FIVE_H + n) =
                make_float2(acc[mt][j][2] + b0, acc[mt][j][3] + b1);
        }
    }
}

// ---- mega: 256 sims CTAs + 320 preact CTAs, occ 2 ----
__global__ __launch_bounds__(256, 2) void k_mega(
    const float* __restrict__ mk, const float* __restrict__ mv,
    float* __restrict__ nk, float* __restrict__ nv,
    const float* __restrict__ bi, const float* __restrict__ bh) {
    extern __shared__ __align__(16) char dsm[];
    if (blockIdx.x < 256) sims_body(dsm, mk, mv, nk, nv, blockIdx.x);
    else                  preact_body(dsm, bi, bh, blockIdx.x - 256);
}

// fused: per-b argmax + gates + DND readout + h/c (+bf16 split) + scatter
__global__ __launch_bounds__(256) void k_lstm(
    const float* __restrict__ c_in, const float* __restrict__ mv,
    const int* __restrict__ widx, const float* __restrict__ q,
    float* __restrict__ out) {
    int b_ = blockIdx.x;
    int t = threadIdx.x;
    __shared__ unsigned long long s[128];
    __shared__ int sbesti;
    __shared__ int sflag;
    if (t < 128)
        s[t] = g_ppack[(size_t)(t*2 + (b_ >> 7)) * 128 + (b_ & 127)];
    if (t == 0) sflag = 1;
    __syncthreads();
    for (int st = 64; st > 0; st >>= 1) {
        if (t < st) {
            unsigned long long v = s[t + st];
            if (v > s[t]) s[t] = v;
        }
        __syncthreads();
    }
    if (t == 0) {
        int best = (int)(0x7FFFFFFFu - (unsigned)(s[0] & 0xFFFFFFFFull));
        sbesti = best;
        out[OFF_BEST + b_] = (float)best;
    }
    int myidx = widx[b_];
    if (t > b_ && widx[t] == myidx) sflag = 0;
    __syncthreads();
    int best = sbesti;
    const float* p = g_preact + (size_t)b_ * FIVE_H;
    const float* mrow = mv + (size_t)best * H;
    float ct_r[4];
    #pragma unroll
    for (int r = 0; r < 4; r++) {
        int j = t + r*256;
        int idx = b_ * H + j;
        float f  = sigmoidf_(p[j]);
        float it = sigmoidf_(p[H + j]);
        float o  = sigmoidf_(p[2*H + j]);
        float rr = sigmoidf_(p[3*H + j]);
        float cn = tanhf(p[4*H + j]);
        float m  = tanhf(mrow[j]);
        float ct = f * c_in[idx] + it * cn + rr * m;
        float ht = o * tanhf(ct);
        ct_r[r] = ct;
        out[OFF_H + idx] = ht;
        out[OFF_C + idx] = ct;
        __nv_bfloat16 hi, lo;
        split_bf16(ct, hi, lo);
        g_chi[idx] = hi;
        g_clo[idx] = lo;
    }
    if (sflag) {
        #pragma unroll
        for (int r = 0; r < 4; r++) {
            int j = t + r*256;
            out[OFF_NK + (size_t)myidx*KEY_DIM + j] = q[(size_t)b_*KEY_DIM + j];
            out[OFF_NV + (size_t)myidx*H + j] = ct_r[r];
        }
    }
}

// ---- HMMA tail GEMM: CTA 64x64, 8 warps (2x4), K-chunk 64 ----
#define HSPITCH 72    // bf16 elems per row (144 B)
#define HG_STAGE 36864
#define HG_SMEM (2*HG_STAGE)
template<int WRITE_SPLIT>
__global__ __launch_bounds__(256) void k_hgemm(
    const __nv_bfloat16* __restrict__ Ahi, const __nv_bfloat16* __restrict__ Alo,
    const __nv_bfloat16* __restrict__ Bthi, const __nv_bfloat16* __restrict__ Btlo,
    const float* __restrict__ bias, float* __restrict__ C,
    __nv_bfloat16* __restrict__ Chi, __nv_bfloat16* __restrict__ Clo,
    int M, int N, int K) {
    extern __shared__ __align__(16) char hsm[];
    uint32_t sb32 = smem_u32(hsm);
    int tid = threadIdx.x;
    int lane = tid & 31, wid = tid >> 5;
    int g = lane >> 2, t2 = (lane & 3) * 2;
    int wm = wid >> 2, wn = wid & 3;          // 2 x 4 warps, warp tile 32x16
    int n0 = blockIdx.x * 64;
    int m0 = blockIdx.y * 64;
    int lrow16 = lane & 15, lk8 = (lane >> 4) * 8;
    int brow8 = lane & 7, bk8 = ((lane >> 3) & 1) * 8, bn8 = (lane >> 4) * 8;

    float acc[2][2][4];
    #pragma unroll
    for (int a = 0; a < 2; a++)
        #pragma unroll
        for (int b = 0; b < 2; b++)
            #pragma unroll
            for (int c = 0; c < 4; c++) acc[a][b][c] = 0.f;

    auto issue = [&](int kci, uint32_t bufo) {
        #pragma unroll
        for (int i = 0; i < 2; i++) {
            int u = tid + i*256;              // 64 rows x 8 uint4
            int row = u >> 3, un = u & 7;
            size_t asrc = (size_t)(m0 + row)*K + kci*64 + un*8;
            uint32_t so = bufo + row*144 + un*16;
            cp16(sb32 + so, Ahi + asrc);
            cp16(sb32 + so + 9216, Alo + asrc);
            size_t bsrc = (size_t)(n0 + row)*K + kci*64 + un*8;
            cp16(sb32 + so + 18432, Bthi + bsrc);
            cp16(sb32 + so + 27648, Btlo + bsrc);
        }
    };

    int nch = K / 64;
    issue(0, 0);
    CP_COMMIT();

    for (int kci = 0; kci < nch; kci++) {
        int b = kci & 1;
        uint32_t bufo = (uint32_t)(b * HG_STAGE);
        CP_WAIT0();
        __syncthreads();
        if (kci + 1 < nch) {
            issue(kci + 1, (uint32_t)((1-b) * HG_STAGE));
            CP_COMMIT();
        }
        #pragma unroll
        for (int ks = 0; ks < 4; ks++) {
            uint32_t ah[2][4], al[2][4];
            #pragma unroll
            for (int mt = 0; mt < 2; mt++) {
                uint32_t addr = sb32 + bufo +
                    (uint32_t)((wm*32 + mt*16 + lrow16)*144 + (ks*16 + lk8)*2);
                ldsm_x4(ah[mt][0], ah[mt][1], ah[mt][2], ah[mt][3], addr);
                ldsm_x4(al[mt][0], al[mt][1], al[mt][2], al[mt][3], addr + 9216);
            }
            {
                uint32_t baddr = sb32 + bufo + 18432 +
                    (uint32_t)((wn*16 + bn8 + brow8)*144 + (ks*16 + bk8)*2);
                uint32_t bhf[4], blf[4];
                ldsm_x4(bhf[0], bhf[1], bhf[2], bhf[3], baddr);
                ldsm_x4(blf[0], blf[1], blf[2], blf[3], baddr + 9216);
                #pragma unroll
                for (int mt = 0; mt < 2; mt++) {
                    mma_bf16(acc[mt][0], ah[mt], bhf[0], bhf[1]);
                    mma_bf16(acc[mt][0], ah[mt], blf[0], blf[1]);
                    mma_bf16(acc[mt][0], al[mt], bhf[0], bhf[1]);
                    mma_bf16(acc[mt][1], ah[mt], bhf[2], bhf[3]);
                    mma_bf16(acc[mt][1], ah[mt], blf[2], blf[3]);
                    mma_bf16(acc[mt][1], al[mt], bhf[2], bhf[3]);
                }
            }
        }
    }
    #pragma unroll
    for (int mt = 0; mt < 2; mt++) {
        #pragma unroll
        for (int j = 0; j < 2; j++) {
            int n = n0 + wn*16 + j*8 + t2;
            float b0 = bias[n], b1 = bias[n+1];
            #pragma unroll
            for (int rh = 0; rh < 2; rh++) {
                int m = m0 + wm*32 + mt*16 + g + rh*8;
                float v0 = acc[mt][j][rh*2+0] + b0;
                float v1 = acc[mt][j][rh*2+1] + b1;
                if (WRITE_SPLIT) { v0 = fmaxf(v0, 0.f); v1 = fmaxf(v1, 0.f); }
                *(float2*)(C + (size_t)m*N + n) = make_float2(v0, v1);
                if (WRITE_SPLIT) {
                    __nv_bfloat16 h0,l0,h1,l1;
                    split_bf16(v0, h0, l0);
                    split_bf16(v1, h1, l1);
                    *(unsigned*)(Chi + (size_t)m*N + n) = pack_bf2(h0, h1);
                    *(unsigned*)(Clo + (size_t)m*N + n) = pack_bf2(l0, l1);
                }
            }
        }
    }
}

// per-row: log_softmax stats, entropy, critic value, gumbel-argmax sample
__global__ __launch_bounds__(256) void k_final(
    const float* __restrict__ Wc, const float* __restrict__ bc,
    float* __restrict__ out) {
    int b_ = blockIdx.x;
    int t = threadIdx.x;
    __shared__ float sred[256];
    __shared__ float sgv[256];
    __shared__ int   sgi[256];
    const float* lrow = g_logits + (size_t)b_ * N_ACT;
    float l[4];
    #pragma unroll
    for (int k = 0; k < 4; k++) l[k] = lrow[t + k*256];

    float mx = fmaxf(fmaxf(l[0], l[1]), fmaxf(l[2], l[3]));
    sred[t] = mx; __syncthreads();
    for (int s = 128; s > 0; s >>= 1) {
        if (t < s) sred[t] = fmaxf(sred[t], sred[t+s]);
        __syncthreads();
    }
    mx = sred[0]; __syncthreads();

    float se = 0.f;
    #pragma unroll
    for (int k = 0; k < 4; k++) se += expf(l[k] - mx);
    sred[t] = se; __syncthreads();
    for (int s = 128; s > 0; s >>= 1) {
        if (t < s) sred[t] += sred[t+s];
        __syncthreads();
    }
    float lse = mx + logf(sred[0]); __syncthreads();

    float ent = 0.f;
    #pragma unroll
    for (int k = 0; k < 4; k++) {
        float lp = l[k] - lse;
        ent += expf(lp) * lp;
    }
    sred[t] = ent; __syncthreads();
    for (int s = 128; s > 0; s >>= 1) {
        if (t < s) sred[t] += sred[t+s];
        __syncthreads();
    }
    float entropy = -sred[0]; __syncthreads();

    const float* ha = g_ha + (size_t)b_ * A2C_H;
    float v = ha[t] * Wc[t] + ha[t + 256] * Wc[t + 256];
    sred[t] = v; __syncthreads();
    for (int s = 128; s > 0; s >>= 1) {
        if (t < s) sred[t] += sred[t+s];
        __syncthreads();
    }
    float vt = sred[0] + bc[0];

    float bv = -3.0e38f; int bn = 0;
    #pragma unroll
    for (int k = 0; k < 4; k++) {
        int n = t + k*256;
        float g = gumbel_at(b_ * N_ACT + n);
        float cand = (l[k] - lse) + g;
        if (cand > bv) { bv = cand; bn = n; }
    }
    sgv[t] = bv; sgi[t] = bn; __syncthreads();
    for (int s = 128; s > 0; s >>= 1) {
        if (t < s) {
            if (sgv[t+s] > sgv[t] || (sgv[t+s] == sgv[t] && sgi[t+s] < sgi[t])) {
                sgv[t] = sgv[t+s]; sgi[t] = sgi[t+s];
            }
        }
        __syncthreads();
    }
    if (t == 0) {
        int nbest = sgi[0];
        out[OFF_A + b_] = (float)nbest;
        out[OFF_PROB + b_] = lrow[nbest] - lse;
        out[OFF_V + b_] = vt;
        out[OFF_ENT + b_] = entropy;
    }
}

extern "C" void kernel_launch(void* const* d_in, const int* in_sizes, int n_in,
                              void* d_out, int out_size) {
    const float* obs     = (const float*)d_in[0];
    const float* barcode = (const float*)d_in[1];
    const float* h_in    = (const float*)d_in[2];
    const float* c_in    = (const float*)d_in[3];
    const int*   widx    = (const int*)  d_in[4];
    const float* Wi      = (const float*)d_in[5];
    const float* bi      = (const float*)d_in[6];
    const float* Wh      = (const float*)d_in[7];
    const float* bh      = (const float*)d_in[8];
    const float* mk      = (const float*)d_in[9];
    const float* mv      = (const float*)d_in[10];
    const float* Wa      = (const float*)d_in[11];
    const float* ba      = (const float*)d_in[12];
    const float* Wact    = (const float*)d_in[13];
    const float* bact    = (const float*)d_in[14];
    const float* Wc      = (const float*)d_in[15];
    const float* bc      = (const float*)d_in[16];
    float* out = (float*)d_out;

    float* g_ha_p; cudaGetSymbolAddress((void**)&g_ha_p, g_ha);
    float* g_logits_p; cudaGetSymbolAddress((void**)&g_logits_p, g_logits);
    __nv_bfloat16 *g_chi_p, *g_clo_p, *g_wathi_p, *g_watlo_p,
                  *g_wacthi_p, *g_wactlo_p, *g_hahi_p, *g_halo_p;
    cudaGetSymbolAddress((void**)&g_chi_p, g_chi);
    cudaGetSymbolAddress((void**)&g_clo_p, g_clo);
    cudaGetSymbolAddress((void**)&g_wathi_p, g_wathi);
    cudaGetSymbolAddress((void**)&g_watlo_p, g_watlo);
    cudaGetSymbolAddress((void**)&g_wacthi_p, g_wacthi);
    cudaGetSymbolAddress((void**)&g_wactlo_p, g_wactlo);
    cudaGetSymbolAddress((void**)&g_hahi_p, g_hahi);
    cudaGetSymbolAddress((void**)&g_halo_p, g_halo);

    static int initd = 0;
    if (!initd) {
        cudaFuncSetAttribute(k_mega, cudaFuncAttributeMaxDynamicSharedMemorySize,
                             MEGA_SMEM);
        cudaFuncSetAttribute(k_hgemm<1>, cudaFuncAttributeMaxDynamicSharedMemorySize,
                             HG_SMEM);
        cudaFuncSetAttribute(k_hgemm<0>, cudaFuncAttributeMaxDynamicSharedMemorySize,
                             HG_SMEM);
        initd = 1;
    }

    k_prep<<<256 + 3072 + 3840 + 256, 256>>>(barcode, obs, h_in, Wi, Wh,
                                             Wa, Wact);                   // #1
    k_mega<<<576, 256, MEGA_SMEM>>>(mk, mv, out + OFF_NK, out + OFF_NV,
                                    bi, bh);                              // #2
    k_lstm<<<BB, 256>>>(c_in, mv, widx, barcode, out);                    // #3
    // ha = relu(c_t @ Wa + ba), + bf16 split
    k_hgemm<1><<<dim3(A2C_H/64, BB/64), 256, HG_SMEM>>>(g_chi_p, g_clo_p,
        g_wathi_p, g_watlo_p, ba, g_ha_p, g_hahi_p, g_halo_p,
        BB, A2C_H, H);                                                    // #4 (profiled)
    // logits = ha @ W_actor + b_actor
    k_hgemm<0><<<dim3(N_ACT/64, BB/64), 256, HG_SMEM>>>(g_hahi_p, g_halo_p,
        g_wacthi_p, g_wactlo_p, bact, g_logits_p, nullptr, nullptr,
        BB, N_ACT, A2C_H);                                                // #5
    k_final<<<BB, 256>>>(Wc, bc, out);                                    // #6
}